// round 2
// baseline (speedup 1.0000x reference)
#include <cuda_runtime.h>
#include <cstddef>

// ---------------------------------------------------------------------------
// AFNO: out = irfft2( MLP( rfft2(x) ) ) + (x @ bias_w^T + bias_b)
// B=8, H=W=64, C=768, 4 blocks of 192. All fp32.
// ---------------------------------------------------------------------------

#define B_ 8
#define H_ 64
#define W_ 64
#define C_ 768
#define NBK 4
#define BSZ 192
#define NV 33
#define MTOK (B_ * H_ * NV)     /* 16896 tokens in frequency space */
#define NROW (B_ * H_ * W_)     /* 32768 rows for bias GEMM        */

// Scratch (ping-pong): SB holds Fw / (r1,i1) / Y;  SA holds X / (r2,i2)
__device__ float g_SAR[MTOK * C_];
__device__ float g_SAI[MTOK * C_];
__device__ float g_SBR[MTOK * C_];
__device__ float g_SBI[MTOK * C_];

// Twiddles: e^{-2*pi*i*k/64}, k = 0..31  (TWI = -sin)
__constant__ float TWR[32] = {
  1.0f, 0.99518472667f, 0.98078528040f, 0.95694033573f,
  0.92387953251f, 0.88192126435f, 0.83146961230f, 0.77301045336f,
  0.70710678119f, 0.63439328416f, 0.55557023302f, 0.47139673683f,
  0.38268343236f, 0.29028467725f, 0.19509032202f, 0.09801714033f,
  0.0f, -0.09801714033f, -0.19509032202f, -0.29028467725f,
  -0.38268343236f, -0.47139673683f, -0.55557023302f, -0.63439328416f,
  -0.70710678119f, -0.77301045336f, -0.83146961230f, -0.88192126435f,
  -0.92387953251f, -0.95694033573f, -0.98078528040f, -0.99518472667f
};
__constant__ float TWI[32] = {
  -0.0f, -0.09801714033f, -0.19509032202f, -0.29028467725f,
  -0.38268343236f, -0.47139673683f, -0.55557023302f, -0.63439328416f,
  -0.70710678119f, -0.77301045336f, -0.83146961230f, -0.88192126435f,
  -0.92387953251f, -0.95694033573f, -0.98078528040f, -0.99518472667f,
  -1.0f, -0.99518472667f, -0.98078528040f, -0.95694033573f,
  -0.92387953251f, -0.88192126435f, -0.83146961230f, -0.77301045336f,
  -0.70710678119f, -0.63439328416f, -0.55557023302f, -0.47139673683f,
  -0.38268343236f, -0.29028467725f, -0.19509032202f, -0.09801714033f
};

// Fully-unrolled 64-point radix-2 DIT FFT on a register array.
// INV=false: X[u] = sum_h v[h] e^{-2pi i u h / 64}; INV=true: conj twiddles.
template<bool INV>
__device__ __forceinline__ void fft64(float2 v[64]) {
  // bit-reversal permutation (indices constant-fold after unroll)
#pragma unroll
  for (int i = 0; i < 64; ++i) {
    int j = ((i & 1) << 5) | ((i & 2) << 3) | ((i & 4) << 1) |
            ((i & 8) >> 1) | ((i & 16) >> 3) | ((i & 32) >> 5);
    if (j > i) { float2 t = v[i]; v[i] = v[j]; v[j] = t; }
  }
#pragma unroll
  for (int s = 1; s <= 6; ++s) {
    const int m = 1 << s, half = m >> 1, stp = 64 >> s;
#pragma unroll
    for (int g = 0; g < 64; g += m) {
#pragma unroll
      for (int t = 0; t < half; ++t) {
        float wr = TWR[t * stp];
        float wi = INV ? -TWI[t * stp] : TWI[t * stp];
        float2 bv = v[g + t + half];
        float tr = bv.x * wr - bv.y * wi;
        float ti = bv.x * wi + bv.y * wr;
        float2 av = v[g + t];
        v[g + t]        = make_float2(av.x + tr, av.y + ti);
        v[g + t + half] = make_float2(av.x - tr, av.y - ti);
      }
    }
  }
}

// ---------------------------------------------------------------------------
// K2: rfft along W (per b,h,c). x[b,h,w,c] -> Fw[b,h,v,c], v=0..32, scale 1/8
// ---------------------------------------------------------------------------
__global__ void k_fft_w_fwd(const float* __restrict__ x,
                            float* __restrict__ FR, float* __restrict__ FI) {
  int idx = blockIdx.x * blockDim.x + threadIdx.x;
  if (idx >= NROW * 12) return;          // B*H*C = 393216 threads
  int c = idx % C_;
  int bh = idx / C_;                     // b*64 + h
  const float* xp = x + (size_t)bh * W_ * C_ + c;
  float2 v[64];
#pragma unroll
  for (int w = 0; w < 64; ++w) v[w] = make_float2(xp[(size_t)w * C_], 0.0f);
  fft64<false>(v);
  size_t ob = (size_t)bh * NV * C_ + c;
#pragma unroll
  for (int f = 0; f < NV; ++f) {
    FR[ob + (size_t)f * C_] = 0.125f * v[f].x;
    FI[ob + (size_t)f * C_] = 0.125f * v[f].y;
  }
}

// ---------------------------------------------------------------------------
// K3/K5: complex FFT along H (per b,v,c), layout [(b*64+h)*33+v]*768+c
// ---------------------------------------------------------------------------
template<bool INV>
__global__ void k_fft_h(const float* __restrict__ IR, const float* __restrict__ II,
                        float* __restrict__ OR_, float* __restrict__ OI_) {
  int idx = blockIdx.x * blockDim.x + threadIdx.x;
  if (idx >= B_ * NV * C_) return;       // 202752 threads
  int c = idx % C_;
  int bv = idx / C_;
  int vf = bv % NV;
  int b = bv / NV;
  size_t base = ((size_t)b * H_ * NV + vf) * C_ + c;   // + h*NV*C_
  const size_t hs = (size_t)NV * C_;
  float2 v[64];
#pragma unroll
  for (int h = 0; h < 64; ++h)
    v[h] = make_float2(IR[base + h * hs], II[base + h * hs]);
  fft64<INV>(v);
#pragma unroll
  for (int u = 0; u < 64; ++u) {
    OR_[base + u * hs] = 0.125f * v[u].x;
    OI_[base + u * hs] = 0.125f * v[u].y;
  }
}

// ---------------------------------------------------------------------------
// K6: irfft along W (per b,h,c). Hermitian-extend 33 bins -> ifft64 -> real,
// accumulate into out (which already holds the bias GEMM result).
// ---------------------------------------------------------------------------
__global__ void k_fft_w_inv(const float* __restrict__ YR, const float* __restrict__ YI,
                            float* __restrict__ out) {
  int idx = blockIdx.x * blockDim.x + threadIdx.x;
  if (idx >= NROW * 12) return;          // B*H*C threads
  int c = idx % C_;
  int bh = idx / C_;
  size_t ib = (size_t)bh * NV * C_ + c;
  float2 v[64];
#pragma unroll
  for (int f = 0; f < NV; ++f)
    v[f] = make_float2(YR[ib + (size_t)f * C_], YI[ib + (size_t)f * C_]);
#pragma unroll
  for (int f = NV; f < 64; ++f)
    v[f] = make_float2(v[64 - f].x, -v[64 - f].y);    // conj extension
  fft64<true>(v);
  float* op = out + (size_t)bh * W_ * C_ + c;
#pragma unroll
  for (int w = 0; w < 64; ++w)
    op[(size_t)w * C_] = op[(size_t)w * C_] + 0.125f * v[w].x;
}

// ---------------------------------------------------------------------------
// K1: bias GEMM  out[n,i] = sum_j x[n,j] * bias_w[i,j] + bias_b[i]
// 64x64 tile, BK=16, 256 threads, 4x4 micro-tile.
// ---------------------------------------------------------------------------
__global__ __launch_bounds__(256)
void k_gemm_bias(const float* __restrict__ A, const float* __restrict__ Wt,
                 const float* __restrict__ bias, float* __restrict__ Cmat) {
  __shared__ float As[16][65];
  __shared__ float Bs[16][65];
  int tx = threadIdx.x, ty = threadIdx.y;
  int tid = ty * 16 + tx;
  int m0 = blockIdx.x * 64, n0 = blockIdx.y * 64;
  float acc[4][4] = {};
  for (int kk = 0; kk < 768; kk += 16) {
#pragma unroll
    for (int l = 0; l < 4; ++l) {
      int e = tid + l * 256;
      int k = e & 15, m = e >> 4;
      As[k][m] = A[(size_t)(m0 + m) * 768 + kk + k];
    }
#pragma unroll
    for (int l = 0; l < 4; ++l) {
      int e = tid + l * 256;
      int k = e & 15, n = e >> 4;
      Bs[k][n] = Wt[(size_t)(n0 + n) * 768 + kk + k];
    }
    __syncthreads();
#pragma unroll
    for (int k = 0; k < 16; ++k) {
      float a[4], b[4];
#pragma unroll
      for (int i = 0; i < 4; ++i) a[i] = As[k][ty * 4 + i];
#pragma unroll
      for (int j = 0; j < 4; ++j) b[j] = Bs[k][tx * 4 + j];
#pragma unroll
      for (int i = 0; i < 4; ++i)
#pragma unroll
        for (int j = 0; j < 4; ++j) acc[i][j] += a[i] * b[j];
    }
    __syncthreads();
  }
#pragma unroll
  for (int i = 0; i < 4; ++i)
#pragma unroll
    for (int j = 0; j < 4; ++j)
      Cmat[(size_t)(m0 + ty * 4 + i) * 768 + n0 + tx * 4 + j] =
          acc[i][j] + bias[n0 + tx * 4 + j];
}

// ---------------------------------------------------------------------------
// K4: block-diagonal complex-MLP GEMM pass.
// Out[t, kb*192+j] = act( sum_d P[t,kb*192+d]*Wp[kb,d,j]
//                       + sgn * sum_d Q[t,kb*192+d]*Wq[kb,d,j] + bias[kb,j] )
// M = 16896, N tiles: 12 (each inside one 192-wide block).
// ---------------------------------------------------------------------------
__global__ __launch_bounds__(256)
void k_mlp_gemm(const float* __restrict__ P, const float* __restrict__ Q,
                const float* __restrict__ Wp, const float* __restrict__ Wq,
                const float* __restrict__ bias, float sgn, int relu,
                float* __restrict__ Out) {
  __shared__ float As[16][65];
  __shared__ float Bs[16][65];
  int tx = threadIdx.x, ty = threadIdx.y;
  int tid = ty * 16 + tx;
  int m0 = blockIdx.x * 64;
  int nt = blockIdx.y;              // 0..11
  int kb = nt / 3;                  // block index
  int j0 = (nt % 3) * 64;           // col offset within block
  float acc[4][4] = {};
#pragma unroll
  for (int phase = 0; phase < 2; ++phase) {
    const float* Ap = phase ? Q : P;
    const float* Wm = phase ? Wq : Wp;
    float s = phase ? sgn : 1.0f;
    for (int kk = 0; kk < 192; kk += 16) {
#pragma unroll
      for (int l = 0; l < 4; ++l) {
        int e = tid + l * 256;
        int k = e & 15, m = e >> 4;
        As[k][m] = Ap[(size_t)(m0 + m) * 768 + kb * 192 + kk + k];
      }
#pragma unroll
      for (int l = 0; l < 4; ++l) {
        int e = tid + l * 256;
        int n = e & 63, k = e >> 6;
        Bs[k][n] = s * Wm[(size_t)(kb * 192 + kk + k) * 192 + j0 + n];
      }
      __syncthreads();
#pragma unroll
      for (int k = 0; k < 16; ++k) {
        float a[4], b[4];
#pragma unroll
        for (int i = 0; i < 4; ++i) a[i] = As[k][ty * 4 + i];
#pragma unroll
        for (int j = 0; j < 4; ++j) b[j] = Bs[k][tx * 4 + j];
#pragma unroll
        for (int i = 0; i < 4; ++i)
#pragma unroll
          for (int j = 0; j < 4; ++j) acc[i][j] += a[i] * b[j];
      }
      __syncthreads();
    }
  }
#pragma unroll
  for (int i = 0; i < 4; ++i)
#pragma unroll
    for (int j = 0; j < 4; ++j) {
      float vv = acc[i][j] + bias[kb * 192 + j0 + tx * 4 + j];
      if (relu) vv = fmaxf(vv, 0.0f);
      Out[(size_t)(m0 + ty * 4 + i) * 768 + kb * 192 + j0 + tx * 4 + j] = vv;
    }
}

// ---------------------------------------------------------------------------
extern "C" void kernel_launch(void* const* d_in, const int* in_sizes, int n_in,
                              void* d_out, int out_size) {
  const float* x  = (const float*)d_in[0];
  const float* w1 = (const float*)d_in[1];   // (2,4,192,192)
  const float* b1 = (const float*)d_in[2];   // (2,4,192)
  const float* w2 = (const float*)d_in[3];
  const float* b2 = (const float*)d_in[4];
  const float* bw = (const float*)d_in[5];   // (768,768)
  const float* bb = (const float*)d_in[6];   // (768,)
  float* out = (float*)d_out;

  float *SAR, *SAI, *SBR, *SBI;
  cudaGetSymbolAddress((void**)&SAR, g_SAR);
  cudaGetSymbolAddress((void**)&SAI, g_SAI);
  cudaGetSymbolAddress((void**)&SBR, g_SBR);
  cudaGetSymbolAddress((void**)&SBI, g_SBI);

  const int WOFF = NBK * BSZ * BSZ;   // 147456: offset of w[1] in (2,...)
  const int BOFF = NBK * BSZ;         // 768:    offset of b[1]

  dim3 blk(16, 16);

  // 1) bias GEMM -> out
  k_gemm_bias<<<dim3(NROW / 64, 12), blk>>>(x, bw, bb, out);

  // 2) forward rfft along W  (x -> SB)   [FIX: use resolved device pointers]
  k_fft_w_fwd<<<(NROW * 12) / 256, 256>>>(x, SBR, SBI);

  // 3) forward fft along H   (SB -> SA)
  k_fft_h<false><<<(B_ * NV * C_) / 256, 256>>>(SBR, SBI, SAR, SAI);

  // 4) layer 1: r1 = relu(Xr*W1r - Xi*W1i + b1r) -> SBR
  k_mlp_gemm<<<dim3(MTOK / 64, 12), blk>>>(SAR, SAI, w1, w1 + WOFF, b1,
                                           -1.0f, 1, SBR);
  //    i1 = relu(Xr*W1i + Xi*W1r + b1i) -> SBI
  k_mlp_gemm<<<dim3(MTOK / 64, 12), blk>>>(SAR, SAI, w1 + WOFF, w1, b1 + BOFF,
                                           1.0f, 1, SBI);
  // 5) layer 2: r2 = r1*W2r - i1*W2i + b2r -> SAR (Xr dead)
  k_mlp_gemm<<<dim3(MTOK / 64, 12), blk>>>(SBR, SBI, w2, w2 + WOFF, b2,
                                           -1.0f, 0, SAR);
  //    i2 = r2*W2i + i1*W2r + b2i -> SAI   (uses the NEW r2, as in reference)
  k_mlp_gemm<<<dim3(MTOK / 64, 12), blk>>>(SAR, SBI, w2 + WOFF, w2, b2 + BOFF,
                                           1.0f, 0, SAI);

  // 6) inverse fft along H   (SA -> SB)
  k_fft_h<true><<<(B_ * NV * C_) / 256, 256>>>(SAR, SAI, SBR, SBI);

  // 7) inverse rfft along W, accumulate into out
  k_fft_w_inv<<<(NROW * 12) / 256, 256>>>(SBR, SBI, out);
}

// round 3
// speedup vs baseline: 1.8840x; 1.8840x over previous
#include <cuda_runtime.h>
#include <cstdint>
#include <cstddef>

// ---------------------------------------------------------------------------
// AFNO: out = irfft2( MLP( rfft2(x) ) ) + (x @ bias_w^T + bias_b)
// B=8, H=W=64, C=768, 4 blocks of 192. GEMMs via tf32 mma.sync.
// ---------------------------------------------------------------------------

#define B_ 8
#define H_ 64
#define W_ 64
#define C_ 768
#define NBK 4
#define BSZ 192
#define NV 33
#define MTOK (B_ * H_ * NV)     /* 16896 tokens in frequency space */
#define NROW (B_ * H_ * W_)     /* 32768 rows for bias GEMM        */

__device__ float g_SAR[MTOK * C_];
__device__ float g_SAI[MTOK * C_];
__device__ float g_SBR[MTOK * C_];
__device__ float g_SBI[MTOK * C_];

// Twiddles: e^{-2*pi*i*k/64}, k = 0..31  (TWI = -sin)
__constant__ float TWR[32] = {
  1.0f, 0.99518472667f, 0.98078528040f, 0.95694033573f,
  0.92387953251f, 0.88192126435f, 0.83146961230f, 0.77301045336f,
  0.70710678119f, 0.63439328416f, 0.55557023302f, 0.47139673683f,
  0.38268343236f, 0.29028467725f, 0.19509032202f, 0.09801714033f,
  0.0f, -0.09801714033f, -0.19509032202f, -0.29028467725f,
  -0.38268343236f, -0.47139673683f, -0.55557023302f, -0.63439328416f,
  -0.70710678119f, -0.77301045336f, -0.83146961230f, -0.88192126435f,
  -0.92387953251f, -0.95694033573f, -0.98078528040f, -0.99518472667f
};
__constant__ float TWI[32] = {
  -0.0f, -0.09801714033f, -0.19509032202f, -0.29028467725f,
  -0.38268343236f, -0.47139673683f, -0.55557023302f, -0.63439328416f,
  -0.70710678119f, -0.77301045336f, -0.83146961230f, -0.88192126435f,
  -0.92387953251f, -0.95694033573f, -0.98078528040f, -0.99518472667f,
  -1.0f, -0.99518472667f, -0.98078528040f, -0.95694033573f,
  -0.92387953251f, -0.88192126435f, -0.83146961230f, -0.77301045336f,
  -0.70710678119f, -0.63439328416f, -0.55557023302f, -0.47139673683f,
  -0.38268343236f, -0.29028467725f, -0.19509032202f, -0.09801714033f
};

template<bool INV>
__device__ __forceinline__ void fft64(float2 v[64]) {
#pragma unroll
  for (int i = 0; i < 64; ++i) {
    int j = ((i & 1) << 5) | ((i & 2) << 3) | ((i & 4) << 1) |
            ((i & 8) >> 1) | ((i & 16) >> 3) | ((i & 32) >> 5);
    if (j > i) { float2 t = v[i]; v[i] = v[j]; v[j] = t; }
  }
#pragma unroll
  for (int s = 1; s <= 6; ++s) {
    const int m = 1 << s, half = m >> 1, stp = 64 >> s;
#pragma unroll
    for (int g = 0; g < 64; g += m) {
#pragma unroll
      for (int t = 0; t < half; ++t) {
        float wr = TWR[t * stp];
        float wi = INV ? -TWI[t * stp] : TWI[t * stp];
        float2 bv = v[g + t + half];
        float tr = bv.x * wr - bv.y * wi;
        float ti = bv.x * wi + bv.y * wr;
        float2 av = v[g + t];
        v[g + t]        = make_float2(av.x + tr, av.y + ti);
        v[g + t + half] = make_float2(av.x - tr, av.y - ti);
      }
    }
  }
}

// ---------------------------------------------------------------------------
// FFT kernels (unchanged from R2)
// ---------------------------------------------------------------------------
__global__ void k_fft_w_fwd(const float* __restrict__ x,
                            float* __restrict__ FR, float* __restrict__ FI) {
  int idx = blockIdx.x * blockDim.x + threadIdx.x;
  if (idx >= NROW * 12) return;
  int c = idx % C_;
  int bh = idx / C_;
  const float* xp = x + (size_t)bh * W_ * C_ + c;
  float2 v[64];
#pragma unroll
  for (int w = 0; w < 64; ++w) v[w] = make_float2(xp[(size_t)w * C_], 0.0f);
  fft64<false>(v);
  size_t ob = (size_t)bh * NV * C_ + c;
#pragma unroll
  for (int f = 0; f < NV; ++f) {
    FR[ob + (size_t)f * C_] = 0.125f * v[f].x;
    FI[ob + (size_t)f * C_] = 0.125f * v[f].y;
  }
}

template<bool INV>
__global__ void k_fft_h(const float* __restrict__ IR, const float* __restrict__ II,
                        float* __restrict__ OR_, float* __restrict__ OI_) {
  int idx = blockIdx.x * blockDim.x + threadIdx.x;
  if (idx >= B_ * NV * C_) return;
  int c = idx % C_;
  int bv = idx / C_;
  int vf = bv % NV;
  int b = bv / NV;
  size_t base = ((size_t)b * H_ * NV + vf) * C_ + c;
  const size_t hs = (size_t)NV * C_;
  float2 v[64];
#pragma unroll
  for (int h = 0; h < 64; ++h)
    v[h] = make_float2(IR[base + h * hs], II[base + h * hs]);
  fft64<INV>(v);
#pragma unroll
  for (int u = 0; u < 64; ++u) {
    OR_[base + u * hs] = 0.125f * v[u].x;
    OI_[base + u * hs] = 0.125f * v[u].y;
  }
}

__global__ void k_fft_w_inv(const float* __restrict__ YR, const float* __restrict__ YI,
                            float* __restrict__ out) {
  int idx = blockIdx.x * blockDim.x + threadIdx.x;
  if (idx >= NROW * 12) return;
  int c = idx % C_;
  int bh = idx / C_;
  size_t ib = (size_t)bh * NV * C_ + c;
  float2 v[64];
#pragma unroll
  for (int f = 0; f < NV; ++f)
    v[f] = make_float2(YR[ib + (size_t)f * C_], YI[ib + (size_t)f * C_]);
#pragma unroll
  for (int f = NV; f < 64; ++f)
    v[f] = make_float2(v[64 - f].x, -v[64 - f].y);
  fft64<true>(v);
  float* op = out + (size_t)bh * W_ * C_ + c;
#pragma unroll
  for (int w = 0; w < 64; ++w)
    op[(size_t)w * C_] = op[(size_t)w * C_] + 0.125f * v[w].x;
}

// ---------------------------------------------------------------------------
// tf32 mma helpers
// ---------------------------------------------------------------------------
__device__ __forceinline__ uint32_t f2tf32(float f) {
  uint32_t u;
  asm("cvt.rna.tf32.f32 %0, %1;" : "=r"(u) : "f"(f));
  return u;
}

__device__ __forceinline__ void mma_tf32(float c[4],
                                         const uint32_t a[4],
                                         const uint32_t b[2]) {
  asm volatile(
      "mma.sync.aligned.m16n8k8.row.col.f32.tf32.tf32.f32 "
      "{%0,%1,%2,%3}, {%4,%5,%6,%7}, {%8,%9}, {%0,%1,%2,%3};"
      : "+f"(c[0]), "+f"(c[1]), "+f"(c[2]), "+f"(c[3])
      : "r"(a[0]), "r"(a[1]), "r"(a[2]), "r"(a[3]), "r"(b[0]), "r"(b[1]));
}

#define ASTR 136   /* smem k-major stride for BM=128 (+8 pad): banks 8*tig+gid */

// ---------------------------------------------------------------------------
// Bias GEMM (tf32 mma): out[m,n] = sum_k x[m,k]*bias_w[n,k] + bias_b[n]
// BM=128, BN=128, BK=32. 8 warps (4m x 2n), warp tile 32x64.
// ---------------------------------------------------------------------------
__global__ __launch_bounds__(256)
void k_gemm_bias_mma(const float* __restrict__ A, const float* __restrict__ Wt,
                     const float* __restrict__ bias, float* __restrict__ Cmat) {
  __shared__ uint32_t As[32 * ASTR];   // [k][m], 17408 B
  __shared__ uint32_t Bs[32 * ASTR];   // [k][n], 17408 B
  int tid = threadIdx.x;
  int lane = tid & 31, wid = tid >> 5;
  int wm = wid & 3, wn = wid >> 2;
  int gid = lane >> 2, tig = lane & 3;
  int m0 = blockIdx.x * 128, n0 = blockIdx.y * 128;

  float acc[2][8][4];
#pragma unroll
  for (int i = 0; i < 2; ++i)
#pragma unroll
    for (int j = 0; j < 8; ++j)
#pragma unroll
      for (int l = 0; l < 4; ++l) acc[i][j][l] = 0.0f;

  for (int kb = 0; kb < 768; kb += 32) {
    // A: 128 rows x 8 float4 = 1024 float4, 4 per thread
#pragma unroll
    for (int l = 0; l < 4; ++l) {
      int f = tid + l * 256;
      int row = f >> 3, kq = f & 7;
      float4 v = *(const float4*)&A[(size_t)(m0 + row) * 768 + kb + kq * 4];
      As[(kq * 4 + 0) * ASTR + row] = f2tf32(v.x);
      As[(kq * 4 + 1) * ASTR + row] = f2tf32(v.y);
      As[(kq * 4 + 2) * ASTR + row] = f2tf32(v.z);
      As[(kq * 4 + 3) * ASTR + row] = f2tf32(v.w);
    }
    // B: Bs[k][n] = Wt[n][k] (transpose on store)
#pragma unroll
    for (int l = 0; l < 4; ++l) {
      int f = tid + l * 256;
      int n = f >> 3, kq = f & 7;
      float4 v = *(const float4*)&Wt[(size_t)(n0 + n) * 768 + kb + kq * 4];
      Bs[(kq * 4 + 0) * ASTR + n] = f2tf32(v.x);
      Bs[(kq * 4 + 1) * ASTR + n] = f2tf32(v.y);
      Bs[(kq * 4 + 2) * ASTR + n] = f2tf32(v.z);
      Bs[(kq * 4 + 3) * ASTR + n] = f2tf32(v.w);
    }
    __syncthreads();
#pragma unroll
    for (int ks = 0; ks < 32; ks += 8) {
      uint32_t af[2][4], bf[8][2];
#pragma unroll
      for (int mi = 0; mi < 2; ++mi) {
        int mr = wm * 32 + mi * 16 + gid;
        af[mi][0] = As[(ks + tig) * ASTR + mr];
        af[mi][1] = As[(ks + tig) * ASTR + mr + 8];
        af[mi][2] = As[(ks + tig + 4) * ASTR + mr];
        af[mi][3] = As[(ks + tig + 4) * ASTR + mr + 8];
      }
#pragma unroll
      for (int ni = 0; ni < 8; ++ni) {
        int nc = wn * 64 + ni * 8 + gid;
        bf[ni][0] = Bs[(ks + tig) * ASTR + nc];
        bf[ni][1] = Bs[(ks + tig + 4) * ASTR + nc];
      }
#pragma unroll
      for (int mi = 0; mi < 2; ++mi)
#pragma unroll
        for (int ni = 0; ni < 8; ++ni) mma_tf32(acc[mi][ni], af[mi], bf[ni]);
    }
    __syncthreads();
  }
#pragma unroll
  for (int mi = 0; mi < 2; ++mi)
#pragma unroll
    for (int ni = 0; ni < 8; ++ni) {
      int row = m0 + wm * 32 + mi * 16 + gid;
      int col = n0 + wn * 64 + ni * 8 + 2 * tig;
      float b0 = bias[col], b1 = bias[col + 1];
      *(float2*)&Cmat[(size_t)row * 768 + col] =
          make_float2(acc[mi][ni][0] + b0, acc[mi][ni][1] + b1);
      *(float2*)&Cmat[(size_t)(row + 8) * 768 + col] =
          make_float2(acc[mi][ni][2] + b0, acc[mi][ni][3] + b1);
    }
}

// ---------------------------------------------------------------------------
// Block-diagonal complex MLP pass (tf32 mma):
// Out[t, kb*192+j] = act( P[t,blk]·Wp[kb] + sgn * Q[t,blk]·Wq[kb] + bias )
// BM=128, BN=64, BK=32. 8 warps (4m x 2n), warp tile 32x32.
// ---------------------------------------------------------------------------
#define BSTR 72
__global__ __launch_bounds__(256)
void k_mlp_mma(const float* __restrict__ P, const float* __restrict__ Q,
               const float* __restrict__ Wp, const float* __restrict__ Wq,
               const float* __restrict__ bias, float sgn, int relu,
               float* __restrict__ Out) {
  __shared__ uint32_t As[32 * ASTR];   // 17408 B
  __shared__ uint32_t Bs[32 * BSTR];   // 9216 B
  int tid = threadIdx.x;
  int lane = tid & 31, wid = tid >> 5;
  int wm = wid & 3, wn = wid >> 2;
  int gid = lane >> 2, tig = lane & 3;
  int m0 = blockIdx.x * 128;
  int nt = blockIdx.y;
  int kb = nt / 3, j0 = (nt % 3) * 64;

  float acc[2][4][4];
#pragma unroll
  for (int i = 0; i < 2; ++i)
#pragma unroll
    for (int j = 0; j < 4; ++j)
#pragma unroll
      for (int l = 0; l < 4; ++l) acc[i][j][l] = 0.0f;

#pragma unroll
  for (int phase = 0; phase < 2; ++phase) {
    const float* Ap = phase ? Q : P;
    const float* Wm_ = phase ? Wq : Wp;
    float s = phase ? sgn : 1.0f;
    for (int kb32 = 0; kb32 < 192; kb32 += 32) {
      // A: 128 rows x 8 float4, 4 per thread
#pragma unroll
      for (int l = 0; l < 4; ++l) {
        int f = tid + l * 256;
        int row = f >> 3, kq = f & 7;
        float4 v = *(const float4*)&Ap[(size_t)(m0 + row) * 768 +
                                       kb * 192 + kb32 + kq * 4];
        As[(kq * 4 + 0) * ASTR + row] = f2tf32(v.x);
        As[(kq * 4 + 1) * ASTR + row] = f2tf32(v.y);
        As[(kq * 4 + 2) * ASTR + row] = f2tf32(v.z);
        As[(kq * 4 + 3) * ASTR + row] = f2tf32(v.w);
      }
      // B: 32 k-rows x 16 float4 = 512 float4, 2 per thread (row k -> n contig)
#pragma unroll
      for (int l = 0; l < 2; ++l) {
        int f = tid + l * 256;
        int k = f >> 4, nq = f & 15;
        float4 v = *(const float4*)&Wm_[(size_t)(kb * 192 + kb32 + k) * 192 +
                                        j0 + nq * 4];
        uint4 u = make_uint4(f2tf32(s * v.x), f2tf32(s * v.y),
                             f2tf32(s * v.z), f2tf32(s * v.w));
        *(uint4*)&Bs[k * BSTR + nq * 4] = u;
      }
      __syncthreads();
#pragma unroll
      for (int ks = 0; ks < 32; ks += 8) {
        uint32_t af[2][4], bf[4][2];
#pragma unroll
        for (int mi = 0; mi < 2; ++mi) {
          int mr = wm * 32 + mi * 16 + gid;
          af[mi][0] = As[(ks + tig) * ASTR + mr];
          af[mi][1] = As[(ks + tig) * ASTR + mr + 8];
          af[mi][2] = As[(ks + tig + 4) * ASTR + mr];
          af[mi][3] = As[(ks + tig + 4) * ASTR + mr + 8];
        }
#pragma unroll
        for (int ni = 0; ni < 4; ++ni) {
          int nc = wn * 32 + ni * 8 + gid;
          bf[ni][0] = Bs[(ks + tig) * BSTR + nc];
          bf[ni][1] = Bs[(ks + tig + 4) * BSTR + nc];
        }
#pragma unroll
        for (int mi = 0; mi < 2; ++mi)
#pragma unroll
          for (int ni = 0; ni < 4; ++ni) mma_tf32(acc[mi][ni], af[mi], bf[ni]);
      }
      __syncthreads();
    }
  }
#pragma unroll
  for (int mi = 0; mi < 2; ++mi)
#pragma unroll
    for (int ni = 0; ni < 4; ++ni) {
      int row = m0 + wm * 32 + mi * 16 + gid;
      int colb = j0 + wn * 32 + ni * 8 + 2 * tig;   // within 192-block
      float b0 = bias[kb * 192 + colb], b1 = bias[kb * 192 + colb + 1];
      float v0 = acc[mi][ni][0] + b0, v1 = acc[mi][ni][1] + b1;
      float v2 = acc[mi][ni][2] + b0, v3 = acc[mi][ni][3] + b1;
      if (relu) {
        v0 = fmaxf(v0, 0.0f); v1 = fmaxf(v1, 0.0f);
        v2 = fmaxf(v2, 0.0f); v3 = fmaxf(v3, 0.0f);
      }
      size_t cg = (size_t)kb * 192 + colb;
      *(float2*)&Out[(size_t)row * 768 + cg] = make_float2(v0, v1);
      *(float2*)&Out[(size_t)(row + 8) * 768 + cg] = make_float2(v2, v3);
    }
}

// ---------------------------------------------------------------------------
extern "C" void kernel_launch(void* const* d_in, const int* in_sizes, int n_in,
                              void* d_out, int out_size) {
  const float* x  = (const float*)d_in[0];
  const float* w1 = (const float*)d_in[1];
  const float* b1 = (const float*)d_in[2];
  const float* w2 = (const float*)d_in[3];
  const float* b2 = (const float*)d_in[4];
  const float* bw = (const float*)d_in[5];
  const float* bb = (const float*)d_in[6];
  float* out = (float*)d_out;

  float *SAR, *SAI, *SBR, *SBI;
  cudaGetSymbolAddress((void**)&SAR, g_SAR);
  cudaGetSymbolAddress((void**)&SAI, g_SAI);
  cudaGetSymbolAddress((void**)&SBR, g_SBR);
  cudaGetSymbolAddress((void**)&SBI, g_SBI);

  const int WOFF = NBK * BSZ * BSZ;   // 147456
  const int BOFF = NBK * BSZ;         // 768

  // 1) bias GEMM -> out  (tf32 mma)
  k_gemm_bias_mma<<<dim3(NROW / 128, 6), 256>>>(x, bw, bb, out);

  // 2) forward rfft along W  (x -> SB)
  k_fft_w_fwd<<<(NROW * 12) / 256, 256>>>(x, SBR, SBI);

  // 3) forward fft along H   (SB -> SA)
  k_fft_h<false><<<(B_ * NV * C_) / 256, 256>>>(SBR, SBI, SAR, SAI);

  // 4) layer 1
  k_mlp_mma<<<dim3(MTOK / 128, 12), 256>>>(SAR, SAI, w1, w1 + WOFF, b1,
                                           -1.0f, 1, SBR);
  k_mlp_mma<<<dim3(MTOK / 128, 12), 256>>>(SAR, SAI, w1 + WOFF, w1, b1 + BOFF,
                                           1.0f, 1, SBI);
  // 5) layer 2 (i2 uses the NEW r2, as in reference)
  k_mlp_mma<<<dim3(MTOK / 128, 12), 256>>>(SBR, SBI, w2, w2 + WOFF, b2,
                                           -1.0f, 0, SAR);
  k_mlp_mma<<<dim3(MTOK / 128, 12), 256>>>(SAR, SBI, w2 + WOFF, w2, b2 + BOFF,
                                           1.0f, 0, SAI);

  // 6) inverse fft along H   (SA -> SB)
  k_fft_h<true><<<(B_ * NV * C_) / 256, 256>>>(SAR, SAI, SBR, SBI);

  // 7) inverse rfft along W, accumulate into out
  k_fft_w_inv<<<(NROW * 12) / 256, 256>>>(SBR, SBI, out);
}

// round 4
// speedup vs baseline: 2.7420x; 1.4554x over previous
#include <cuda_runtime.h>
#include <cuda_fp16.h>
#include <cstdint>
#include <cstddef>

// ---------------------------------------------------------------------------
// AFNO: out = irfft2( MLP( rfft2(x) ) ) + (x @ bias_w^T + bias_b)
// B=8, H=W=64, C=768, 4 blocks of 192. GEMMs via fp16 mma.sync m16n8k16.
// ---------------------------------------------------------------------------

#define B_ 8
#define H_ 64
#define W_ 64
#define C_ 768
#define NBK 4
#define BSZ 192
#define NV 33
#define MTOK (B_ * H_ * NV)     /* 16896 */
#define NROW (B_ * H_ * W_)     /* 32768 */

__device__ float g_SAR[MTOK * C_];
__device__ float g_SAI[MTOK * C_];
__device__ float g_SBR[MTOK * C_];
__device__ float g_SBI[MTOK * C_];
// composite layer-2 weights for the fused i2 path
__device__ float g_Wc [NBK * BSZ * BSZ];
__device__ float g_Wdm[NBK * BSZ * BSZ];
__device__ float g_bp [NBK * BSZ];

// Twiddles: e^{-2*pi*i*k/64}, k = 0..31  (TWI = -sin)
__constant__ float TWR[32] = {
  1.0f, 0.99518472667f, 0.98078528040f, 0.95694033573f,
  0.92387953251f, 0.88192126435f, 0.83146961230f, 0.77301045336f,
  0.70710678119f, 0.63439328416f, 0.55557023302f, 0.47139673683f,
  0.38268343236f, 0.29028467725f, 0.19509032202f, 0.09801714033f,
  0.0f, -0.09801714033f, -0.19509032202f, -0.29028467725f,
  -0.38268343236f, -0.47139673683f, -0.55557023302f, -0.63439328416f,
  -0.70710678119f, -0.77301045336f, -0.83146961230f, -0.88192126435f,
  -0.92387953251f, -0.95694033573f, -0.98078528040f, -0.99518472667f
};
__constant__ float TWI[32] = {
  -0.0f, -0.09801714033f, -0.19509032202f, -0.29028467725f,
  -0.38268343236f, -0.47139673683f, -0.55557023302f, -0.63439328416f,
  -0.70710678119f, -0.77301045336f, -0.83146961230f, -0.88192126435f,
  -0.92387953251f, -0.95694033573f, -0.98078528040f, -0.99518472667f,
  -1.0f, -0.99518472667f, -0.98078528040f, -0.95694033573f,
  -0.92387953251f, -0.88192126435f, -0.83146961230f, -0.77301045336f,
  -0.70710678119f, -0.63439328416f, -0.55557023302f, -0.47139673683f,
  -0.38268343236f, -0.29028467725f, -0.19509032202f, -0.09801714033f
};

template<bool INV>
__device__ __forceinline__ void fft64(float2 v[64]) {
#pragma unroll
  for (int i = 0; i < 64; ++i) {
    int j = ((i & 1) << 5) | ((i & 2) << 3) | ((i & 4) << 1) |
            ((i & 8) >> 1) | ((i & 16) >> 3) | ((i & 32) >> 5);
    if (j > i) { float2 t = v[i]; v[i] = v[j]; v[j] = t; }
  }
#pragma unroll
  for (int s = 1; s <= 6; ++s) {
    const int m = 1 << s, half = m >> 1, stp = 64 >> s;
#pragma unroll
    for (int g = 0; g < 64; g += m) {
#pragma unroll
      for (int t = 0; t < half; ++t) {
        float wr = TWR[t * stp];
        float wi = INV ? -TWI[t * stp] : TWI[t * stp];
        float2 bv = v[g + t + half];
        float tr = bv.x * wr - bv.y * wi;
        float ti = bv.x * wi + bv.y * wr;
        float2 av = v[g + t];
        v[g + t]        = make_float2(av.x + tr, av.y + ti);
        v[g + t + half] = make_float2(av.x - tr, av.y - ti);
      }
    }
  }
}

// ---------------------------------------------------------------------------
// FFT kernels (unchanged)
// ---------------------------------------------------------------------------
__global__ void k_fft_w_fwd(const float* __restrict__ x,
                            float* __restrict__ FR, float* __restrict__ FI) {
  int idx = blockIdx.x * blockDim.x + threadIdx.x;
  if (idx >= NROW * 12) return;
  int c = idx % C_;
  int bh = idx / C_;
  const float* xp = x + (size_t)bh * W_ * C_ + c;
  float2 v[64];
#pragma unroll
  for (int w = 0; w < 64; ++w) v[w] = make_float2(xp[(size_t)w * C_], 0.0f);
  fft64<false>(v);
  size_t ob = (size_t)bh * NV * C_ + c;
#pragma unroll
  for (int f = 0; f < NV; ++f) {
    FR[ob + (size_t)f * C_] = 0.125f * v[f].x;
    FI[ob + (size_t)f * C_] = 0.125f * v[f].y;
  }
}

template<bool INV>
__global__ void k_fft_h(const float* __restrict__ IR, const float* __restrict__ II,
                        float* __restrict__ OR_, float* __restrict__ OI_) {
  int idx = blockIdx.x * blockDim.x + threadIdx.x;
  if (idx >= B_ * NV * C_) return;
  int c = idx % C_;
  int bv = idx / C_;
  int vf = bv % NV;
  int b = bv / NV;
  size_t base = ((size_t)b * H_ * NV + vf) * C_ + c;
  const size_t hs = (size_t)NV * C_;
  float2 v[64];
#pragma unroll
  for (int h = 0; h < 64; ++h)
    v[h] = make_float2(IR[base + h * hs], II[base + h * hs]);
  fft64<INV>(v);
#pragma unroll
  for (int u = 0; u < 64; ++u) {
    OR_[base + u * hs] = 0.125f * v[u].x;
    OI_[base + u * hs] = 0.125f * v[u].y;
  }
}

__global__ void k_fft_w_inv(const float* __restrict__ YR, const float* __restrict__ YI,
                            float* __restrict__ out) {
  int idx = blockIdx.x * blockDim.x + threadIdx.x;
  if (idx >= NROW * 12) return;
  int c = idx % C_;
  int bh = idx / C_;
  size_t ib = (size_t)bh * NV * C_ + c;
  float2 v[64];
#pragma unroll
  for (int f = 0; f < NV; ++f)
    v[f] = make_float2(YR[ib + (size_t)f * C_], YI[ib + (size_t)f * C_]);
#pragma unroll
  for (int f = NV; f < 64; ++f)
    v[f] = make_float2(v[64 - f].x, -v[64 - f].y);
  fft64<true>(v);
  float* op = out + (size_t)bh * W_ * C_ + c;
#pragma unroll
  for (int w = 0; w < 64; ++w)
    op[(size_t)w * C_] = op[(size_t)w * C_] + 0.125f * v[w].x;
}

// ---------------------------------------------------------------------------
// fp16 mma helpers
// ---------------------------------------------------------------------------
__device__ __forceinline__ uint32_t h2(float a, float b) {
  __half2 h = __floats2half2_rn(a, b);
  return *reinterpret_cast<uint32_t*>(&h);
}

__device__ __forceinline__ void mma_f16(float c[4],
                                        const uint32_t a[4],
                                        const uint32_t b[2]) {
  asm volatile(
      "mma.sync.aligned.m16n8k16.row.col.f32.f16.f16.f32 "
      "{%0,%1,%2,%3}, {%4,%5,%6,%7}, {%8,%9}, {%0,%1,%2,%3};"
      : "+f"(c[0]), "+f"(c[1]), "+f"(c[2]), "+f"(c[3])
      : "r"(a[0]), "r"(a[1]), "r"(a[2]), "r"(a[3]), "r"(b[0]), "r"(b[1]));
}

#define ASTR 136   /* smem kpair-major stride for 128-wide tiles (+8 pad) */
#define BSTR 72    /* stride for 64-wide tiles */

// ---------------------------------------------------------------------------
// Precompute composite layer-2 weights:
//   Wc  = W2r @ W2i          (per block)
//   Wdm = W2r - W2i @ W2i
//   bp  = b2r @ W2i + b2i
// ---------------------------------------------------------------------------
__global__ void k_precomp(const float* __restrict__ w2,
                          const float* __restrict__ b2) {
  int kb = blockIdx.x / BSZ, d = blockIdx.x % BSZ;
  int j = threadIdx.x;
  const float* W2r = w2 + (size_t)kb * BSZ * BSZ;
  const float* W2i = w2 + (size_t)NBK * BSZ * BSZ + (size_t)kb * BSZ * BSZ;
  float accC = 0.0f, accI = 0.0f;
  for (int e = 0; e < BSZ; ++e) {
    float wi = W2i[e * BSZ + j];
    accC += W2r[d * BSZ + e] * wi;
    accI += W2i[d * BSZ + e] * wi;
  }
  g_Wc [((size_t)kb * BSZ + d) * BSZ + j] = accC;
  g_Wdm[((size_t)kb * BSZ + d) * BSZ + j] = W2r[d * BSZ + j] - accI;
  if (d == 0) {
    float accB = 0.0f;
    for (int e = 0; e < BSZ; ++e) accB += b2[kb * BSZ + e] * W2i[e * BSZ + j];
    g_bp[kb * BSZ + j] = accB + b2[NBK * BSZ + kb * BSZ + j];
  }
}

// ---------------------------------------------------------------------------
// Bias GEMM (fp16 mma): out[m,n] = sum_k x[m,k]*bias_w[n,k] + bias_b[n]
// BM=128, BN=128, BK=32. 8 warps (4m x 2n), warp tile 32x64.
// ---------------------------------------------------------------------------
__global__ __launch_bounds__(256)
void k_gemm_bias_f16(const float* __restrict__ A, const float* __restrict__ Wt,
                     const float* __restrict__ bias, float* __restrict__ Cmat) {
  __shared__ uint32_t As2[16 * ASTR];   // [kpair][m] half2
  __shared__ uint32_t Bs2[16 * ASTR];   // [kpair][n] half2
  int tid = threadIdx.x;
  int lane = tid & 31, wid = tid >> 5;
  int wm = wid & 3, wn = wid >> 2;
  int gid = lane >> 2, tig = lane & 3;
  int m0 = blockIdx.x * 128, n0 = blockIdx.y * 128;

  float acc[2][8][4];
#pragma unroll
  for (int i = 0; i < 2; ++i)
#pragma unroll
    for (int j = 0; j < 8; ++j)
#pragma unroll
      for (int l = 0; l < 4; ++l) acc[i][j][l] = 0.0f;

  for (int kb = 0; kb < 768; kb += 32) {
#pragma unroll
    for (int l = 0; l < 4; ++l) {
      int f = tid + l * 256;
      int row = f >> 3, kq = f & 7;
      float4 v = *(const float4*)&A[(size_t)(m0 + row) * 768 + kb + kq * 4];
      As2[(2 * kq) * ASTR + row]     = h2(v.x, v.y);
      As2[(2 * kq + 1) * ASTR + row] = h2(v.z, v.w);
    }
#pragma unroll
    for (int l = 0; l < 4; ++l) {
      int f = tid + l * 256;
      int n = f >> 3, kq = f & 7;
      float4 v = *(const float4*)&Wt[(size_t)(n0 + n) * 768 + kb + kq * 4];
      Bs2[(2 * kq) * ASTR + n]     = h2(v.x, v.y);
      Bs2[(2 * kq + 1) * ASTR + n] = h2(v.z, v.w);
    }
    __syncthreads();
#pragma unroll
    for (int k0 = 0; k0 < 16; k0 += 8) {   // kpair base: 2 MMA k-steps
      uint32_t af[2][4], bf[8][2];
#pragma unroll
      for (int mi = 0; mi < 2; ++mi) {
        int mr = wm * 32 + mi * 16 + gid;
        af[mi][0] = As2[(k0 + tig) * ASTR + mr];
        af[mi][1] = As2[(k0 + tig) * ASTR + mr + 8];
        af[mi][2] = As2[(k0 + tig + 4) * ASTR + mr];
        af[mi][3] = As2[(k0 + tig + 4) * ASTR + mr + 8];
      }
#pragma unroll
      for (int ni = 0; ni < 8; ++ni) {
        int nc = wn * 64 + ni * 8 + gid;
        bf[ni][0] = Bs2[(k0 + tig) * ASTR + nc];
        bf[ni][1] = Bs2[(k0 + tig + 4) * ASTR + nc];
      }
#pragma unroll
      for (int mi = 0; mi < 2; ++mi)
#pragma unroll
        for (int ni = 0; ni < 8; ++ni) mma_f16(acc[mi][ni], af[mi], bf[ni]);
    }
    __syncthreads();
  }
#pragma unroll
  for (int mi = 0; mi < 2; ++mi)
#pragma unroll
    for (int ni = 0; ni < 8; ++ni) {
      int row = m0 + wm * 32 + mi * 16 + gid;
      int col = n0 + wn * 64 + ni * 8 + 2 * tig;
      float b0 = bias[col], b1 = bias[col + 1];
      *(float2*)&Cmat[(size_t)row * 768 + col] =
          make_float2(acc[mi][ni][0] + b0, acc[mi][ni][1] + b1);
      *(float2*)&Cmat[(size_t)(row + 8) * 768 + col] =
          make_float2(acc[mi][ni][2] + b0, acc[mi][ni][3] + b1);
    }
}

// ---------------------------------------------------------------------------
// Fused block-diagonal complex-MLP pass (fp16 mma), TWO outputs per kernel:
//   OutR = act( P·WRa + sR * Q·WRb + bR )
//   OutI = act( P·WIa + sI * Q·WIb + bI )
// A tiles (P, Q) are loaded once and shared by both outputs.
// BM=128, BN=64. 8 warps (4m x 2n), warp tile 32x32 per output.
// ---------------------------------------------------------------------------
__global__ __launch_bounds__(256)
void k_mlp2(const float* __restrict__ P, const float* __restrict__ Q,
            const float* __restrict__ WRa, const float* __restrict__ WRb, float sR,
            const float* __restrict__ WIa, const float* __restrict__ WIb, float sI,
            const float* __restrict__ bR, const float* __restrict__ bI, int relu,
            float* __restrict__ OutR, float* __restrict__ OutI) {
  __shared__ uint32_t As2[16 * ASTR];    // [kpair][m]
  __shared__ uint32_t BsR[16 * BSTR];    // [kpair][n]
  __shared__ uint32_t BsI[16 * BSTR];
  int tid = threadIdx.x;
  int lane = tid & 31, wid = tid >> 5;
  int wm = wid & 3, wn = wid >> 2;
  int gid = lane >> 2, tig = lane & 3;
  int m0 = blockIdx.x * 128;
  int nt = blockIdx.y;
  int kb = nt / 3, j0 = (nt % 3) * 64;

  float accR[2][4][4], accI[2][4][4];
#pragma unroll
  for (int i = 0; i < 2; ++i)
#pragma unroll
    for (int j = 0; j < 4; ++j)
#pragma unroll
      for (int l = 0; l < 4; ++l) { accR[i][j][l] = 0.0f; accI[i][j][l] = 0.0f; }

#pragma unroll
  for (int ph = 0; ph < 2; ++ph) {
    const float* Ap = ph ? Q : P;
    const float* Wr = ph ? WRb : WRa;
    const float* Wi = ph ? WIb : WIa;
    float sr = ph ? sR : 1.0f;
    float si = ph ? sI : 1.0f;
    for (int kk = 0; kk < 192; kk += 32) {
      // A tile: 128 x 32 fp32 -> half2 kpair-major
#pragma unroll
      for (int l = 0; l < 4; ++l) {
        int f = tid + l * 256;
        int row = f >> 3, kq = f & 7;
        float4 v = *(const float4*)&Ap[(size_t)(m0 + row) * 768 +
                                       kb * 192 + kk + kq * 4];
        As2[(2 * kq) * ASTR + row]     = h2(v.x, v.y);
        As2[(2 * kq + 1) * ASTR + row] = h2(v.z, v.w);
      }
      // B tiles (R & I): 32 k-rows x 64 n. One thread: rows (2kp, 2kp+1) x 4 n.
      {
        int kp = tid >> 4, nq = tid & 15;
        size_t base = (size_t)(kb * 192 + kk + 2 * kp) * 192 + j0 + nq * 4;
        float4 r0 = *(const float4*)&Wr[base];
        float4 r1 = *(const float4*)&Wr[base + 192];
        BsR[kp * BSTR + nq * 4 + 0] = h2(sr * r0.x, sr * r1.x);
        BsR[kp * BSTR + nq * 4 + 1] = h2(sr * r0.y, sr * r1.y);
        BsR[kp * BSTR + nq * 4 + 2] = h2(sr * r0.z, sr * r1.z);
        BsR[kp * BSTR + nq * 4 + 3] = h2(sr * r0.w, sr * r1.w);
        float4 s0 = *(const float4*)&Wi[base];
        float4 s1 = *(const float4*)&Wi[base + 192];
        BsI[kp * BSTR + nq * 4 + 0] = h2(si * s0.x, si * s1.x);
        BsI[kp * BSTR + nq * 4 + 1] = h2(si * s0.y, si * s1.y);
        BsI[kp * BSTR + nq * 4 + 2] = h2(si * s0.z, si * s1.z);
        BsI[kp * BSTR + nq * 4 + 3] = h2(si * s0.w, si * s1.w);
      }
      __syncthreads();
#pragma unroll
      for (int k0 = 0; k0 < 16; k0 += 8) {
        uint32_t af[2][4], bfR[4][2], bfI[4][2];
#pragma unroll
        for (int mi = 0; mi < 2; ++mi) {
          int mr = wm * 32 + mi * 16 + gid;
          af[mi][0] = As2[(k0 + tig) * ASTR + mr];
          af[mi][1] = As2[(k0 + tig) * ASTR + mr + 8];
          af[mi][2] = As2[(k0 + tig + 4) * ASTR + mr];
          af[mi][3] = As2[(k0 + tig + 4) * ASTR + mr + 8];
        }
#pragma unroll
        for (int ni = 0; ni < 4; ++ni) {
          int nc = wn * 32 + ni * 8 + gid;
          bfR[ni][0] = BsR[(k0 + tig) * BSTR + nc];
          bfR[ni][1] = BsR[(k0 + tig + 4) * BSTR + nc];
          bfI[ni][0] = BsI[(k0 + tig) * BSTR + nc];
          bfI[ni][1] = BsI[(k0 + tig + 4) * BSTR + nc];
        }
#pragma unroll
        for (int mi = 0; mi < 2; ++mi)
#pragma unroll
          for (int ni = 0; ni < 4; ++ni) {
            mma_f16(accR[mi][ni], af[mi], bfR[ni]);
            mma_f16(accI[mi][ni], af[mi], bfI[ni]);
          }
      }
      __syncthreads();
    }
  }
#pragma unroll
  for (int mi = 0; mi < 2; ++mi)
#pragma unroll
    for (int ni = 0; ni < 4; ++ni) {
      int row = m0 + wm * 32 + mi * 16 + gid;
      int colb = j0 + wn * 32 + ni * 8 + 2 * tig;
      size_t cg = (size_t)kb * 192 + colb;
      float bR0 = bR[kb * 192 + colb], bR1 = bR[kb * 192 + colb + 1];
      float bI0 = bI[kb * 192 + colb], bI1 = bI[kb * 192 + colb + 1];
      float r0 = accR[mi][ni][0] + bR0, r1 = accR[mi][ni][1] + bR1;
      float r2v = accR[mi][ni][2] + bR0, r3 = accR[mi][ni][3] + bR1;
      float i0 = accI[mi][ni][0] + bI0, i1v = accI[mi][ni][1] + bI1;
      float i2v = accI[mi][ni][2] + bI0, i3 = accI[mi][ni][3] + bI1;
      if (relu) {
        r0 = fmaxf(r0, 0.0f); r1 = fmaxf(r1, 0.0f);
        r2v = fmaxf(r2v, 0.0f); r3 = fmaxf(r3, 0.0f);
        i0 = fmaxf(i0, 0.0f); i1v = fmaxf(i1v, 0.0f);
        i2v = fmaxf(i2v, 0.0f); i3 = fmaxf(i3, 0.0f);
      }
      *(float2*)&OutR[(size_t)row * 768 + cg]       = make_float2(r0, r1);
      *(float2*)&OutR[(size_t)(row + 8) * 768 + cg] = make_float2(r2v, r3);
      *(float2*)&OutI[(size_t)row * 768 + cg]       = make_float2(i0, i1v);
      *(float2*)&OutI[(size_t)(row + 8) * 768 + cg] = make_float2(i2v, i3);
    }
}

// ---------------------------------------------------------------------------
extern "C" void kernel_launch(void* const* d_in, const int* in_sizes, int n_in,
                              void* d_out, int out_size) {
  const float* x  = (const float*)d_in[0];
  const float* w1 = (const float*)d_in[1];
  const float* b1 = (const float*)d_in[2];
  const float* w2 = (const float*)d_in[3];
  const float* b2 = (const float*)d_in[4];
  const float* bw = (const float*)d_in[5];
  const float* bb = (const float*)d_in[6];
  float* out = (float*)d_out;

  float *SAR, *SAI, *SBR, *SBI, *Wc, *Wdm, *bp;
  cudaGetSymbolAddress((void**)&SAR, g_SAR);
  cudaGetSymbolAddress((void**)&SAI, g_SAI);
  cudaGetSymbolAddress((void**)&SBR, g_SBR);
  cudaGetSymbolAddress((void**)&SBI, g_SBI);
  cudaGetSymbolAddress((void**)&Wc,  g_Wc);
  cudaGetSymbolAddress((void**)&Wdm, g_Wdm);
  cudaGetSymbolAddress((void**)&bp,  g_bp);

  const int WOFF = NBK * BSZ * BSZ;   // 147456
  const int BOFF = NBK * BSZ;         // 768

  // 1) bias GEMM -> out (fp16 mma)
  k_gemm_bias_f16<<<dim3(NROW / 128, 6), 256>>>(x, bw, bb, out);

  // 2) forward rfft along W  (x -> SB)
  k_fft_w_fwd<<<(NROW * 12) / 256, 256>>>(x, SBR, SBI);

  // 3) composite layer-2 weights (independent; small)
  k_precomp<<<NBK * BSZ, BSZ>>>(w2, b2);

  // 4) forward fft along H   (SB -> SA)
  k_fft_h<false><<<(B_ * NV * C_) / 256, 256>>>(SBR, SBI, SAR, SAI);

  // 5) layer 1 fused: r1 = relu(Xr·W1r - Xi·W1i + b1r)
  //                   i1 = relu(Xr·W1i + Xi·W1r + b1i)
  k_mlp2<<<dim3(MTOK / 128, 12), 256>>>(SAR, SAI,
                                        w1, w1 + WOFF, -1.0f,
                                        w1 + WOFF, w1, 1.0f,
                                        b1, b1 + BOFF, 1, SBR, SBI);

  // 6) layer 2 fused: r2 = r1·W2r - i1·W2i + b2r
  //                   i2 = r1·Wc + i1·Wdm + bp   (== r2·W2i + i1·W2r + b2i)
  k_mlp2<<<dim3(MTOK / 128, 12), 256>>>(SBR, SBI,
                                        w2, w2 + WOFF, -1.0f,
                                        Wc, Wdm, 1.0f,
                                        b2, bp, 0, SAR, SAI);

  // 7) inverse fft along H   (SA -> SB)
  k_fft_h<true><<<(B_ * NV * C_) / 256, 256>>>(SAR, SAI, SBR, SBI);

  // 8) inverse rfft along W, accumulate into out
  k_fft_w_inv<<<(NROW * 12) / 256, 256>>>(SBR, SBI, out);
}

// round 5
// speedup vs baseline: 4.5838x; 1.6717x over previous
#include <cuda_runtime.h>
#include <cuda_fp16.h>
#include <cstdint>
#include <cstddef>

// ---------------------------------------------------------------------------
// AFNO: out = irfft2( MLP( rfft2(x) ) ) + (x @ bias_w^T + bias_b)
// B=8, H=W=64, C=768, 4 blocks of 192. fp16 mma GEMMs + cooperative FFTs.
// ---------------------------------------------------------------------------

#define B_ 8
#define H_ 64
#define W_ 64
#define C_ 768
#define NBK 4
#define BSZ 192
#define NV 33
#define MTOK (B_ * H_ * NV)     /* 16896 */
#define NROW (B_ * H_ * W_)     /* 32768 */

__device__ float g_SAR[MTOK * C_];
__device__ float g_SAI[MTOK * C_];
__device__ float g_SBR[MTOK * C_];
__device__ float g_SBI[MTOK * C_];
__device__ float g_Wc [NBK * BSZ * BSZ];
__device__ float g_Wdm[NBK * BSZ * BSZ];
__device__ float g_bp [NBK * BSZ];

// W64^k = e^{-2pi i k/64}: TW64R = cos, TW64I = -sin, k = 0..63
__constant__ float TW64R[64] = {
  1.0f, 0.99518472667f, 0.98078528040f, 0.95694033573f,
  0.92387953251f, 0.88192126435f, 0.83146961230f, 0.77301045336f,
  0.70710678119f, 0.63439328416f, 0.55557023302f, 0.47139673683f,
  0.38268343236f, 0.29028467725f, 0.19509032202f, 0.09801714033f,
  0.0f, -0.09801714033f, -0.19509032202f, -0.29028467725f,
  -0.38268343236f, -0.47139673683f, -0.55557023302f, -0.63439328416f,
  -0.70710678119f, -0.77301045336f, -0.83146961230f, -0.88192126435f,
  -0.92387953251f, -0.95694033573f, -0.98078528040f, -0.99518472667f,
  -1.0f, -0.99518472667f, -0.98078528040f, -0.95694033573f,
  -0.92387953251f, -0.88192126435f, -0.83146961230f, -0.77301045336f,
  -0.70710678119f, -0.63439328416f, -0.55557023302f, -0.47139673683f,
  -0.38268343236f, -0.29028467725f, -0.19509032202f, -0.09801714033f,
  0.0f, 0.09801714033f, 0.19509032202f, 0.29028467725f,
  0.38268343236f, 0.47139673683f, 0.55557023302f, 0.63439328416f,
  0.70710678119f, 0.77301045336f, 0.83146961230f, 0.88192126435f,
  0.92387953251f, 0.95694033573f, 0.98078528040f, 0.99518472667f
};
__constant__ float TW64I[64] = {
  -0.0f, -0.09801714033f, -0.19509032202f, -0.29028467725f,
  -0.38268343236f, -0.47139673683f, -0.55557023302f, -0.63439328416f,
  -0.70710678119f, -0.77301045336f, -0.83146961230f, -0.88192126435f,
  -0.92387953251f, -0.95694033573f, -0.98078528040f, -0.99518472667f,
  -1.0f, -0.99518472667f, -0.98078528040f, -0.95694033573f,
  -0.92387953251f, -0.88192126435f, -0.83146961230f, -0.77301045336f,
  -0.70710678119f, -0.63439328416f, -0.55557023302f, -0.47139673683f,
  -0.38268343236f, -0.29028467725f, -0.19509032202f, -0.09801714033f,
  0.0f, 0.09801714033f, 0.19509032202f, 0.29028467725f,
  0.38268343236f, 0.47139673683f, 0.55557023302f, 0.63439328416f,
  0.70710678119f, 0.77301045336f, 0.83146961230f, 0.88192126435f,
  0.92387953251f, 0.95694033573f, 0.98078528040f, 0.99518472667f,
  1.0f, 0.99518472667f, 0.98078528040f, 0.95694033573f,
  0.92387953251f, 0.88192126435f, 0.83146961230f, 0.77301045336f,
  0.70710678119f, 0.63439328416f, 0.55557023302f, 0.47139673683f,
  0.38268343236f, 0.29028467725f, 0.19509032202f, 0.09801714033f
};
__constant__ float TW8R[4] = {1.0f, 0.70710678119f, 0.0f, -0.70710678119f};
__constant__ float TW8I[4] = {0.0f, -0.70710678119f, -1.0f, -0.70710678119f};

// 8-point DFT, fully unrolled radix-2 DIT. INV => conj twiddles (no 1/N).
template<bool INV>
__device__ __forceinline__ void dft8(float2 v[8]) {
  float2 t;
  t = v[1]; v[1] = v[4]; v[4] = t;
  t = v[3]; v[3] = v[6]; v[6] = t;
#pragma unroll
  for (int s = 1; s <= 3; ++s) {
    const int m = 1 << s, half = m >> 1, stp = 8 >> s;
#pragma unroll
    for (int g = 0; g < 8; g += m)
#pragma unroll
      for (int q = 0; q < half; ++q) {
        float wr = TW8R[q * stp];
        float wi = INV ? -TW8I[q * stp] : TW8I[q * stp];
        float2 bb = v[g + q + half];
        float tr = bb.x * wr - bb.y * wi;
        float ti = bb.x * wi + bb.y * wr;
        float2 aa = v[g + q];
        v[g + q]        = make_float2(aa.x + tr, aa.y + ti);
        v[g + q + half] = make_float2(aa.x - tr, aa.y - ti);
      }
  }
}

// Stage-1 twiddle: v[d] *= W64^{r*d} (conj if INV). r is warp-uniform.
template<bool INV>
__device__ __forceinline__ void tw64(float2 v[8], int r) {
#pragma unroll
  for (int d = 1; d < 8; ++d) {
    int k = r * d;
    float wr = TW64R[k];
    float wi = INV ? -TW64I[k] : TW64I[k];
    float2 z = v[d];
    v[d] = make_float2(z.x * wr - z.y * wi, z.x * wi + z.y * wr);
  }
}

#define COLP 33   /* smem col stride (32 cols + 1 pad) */

// ---------------------------------------------------------------------------
// K2: rfft along W. 8 threads/column (r = tid>>5), 32 channels/block.
// x[b,h,w,c] -> Fw[b,h,v,c], v=0..32, scale 1/8.
// ---------------------------------------------------------------------------
__global__ __launch_bounds__(256)
void k_fft_w_fwd(const float* __restrict__ x,
                 float* __restrict__ FR, float* __restrict__ FI) {
  __shared__ float2 sm[64 * COLP];
  int tx = threadIdx.x & 31, r = threadIdx.x >> 5;
  int cblk = blockIdx.x % 24;
  int bh = blockIdx.x / 24;
  int c = cblk * 32 + tx;
  const float* xp = x + (size_t)bh * W_ * C_ + c;
  float2 v[8];
#pragma unroll
  for (int a = 0; a < 8; ++a)
    v[a] = make_float2(xp[(size_t)(8 * a + r) * C_], 0.0f);
  dft8<false>(v);
  tw64<false>(v, r);
#pragma unroll
  for (int d = 0; d < 8; ++d) sm[(d * 8 + r) * COLP + tx] = v[d];
  __syncthreads();
  float2 u[8];
#pragma unroll
  for (int b = 0; b < 8; ++b) u[b] = sm[(r * 8 + b) * COLP + tx];
  dft8<false>(u);
  size_t ob = (size_t)bh * NV * C_ + c;
#pragma unroll
  for (int cc = 0; cc < 8; ++cc) {
    int k = 8 * cc + r;
    if (k <= 32) {
      FR[ob + (size_t)k * C_] = 0.125f * u[cc].x;
      FI[ob + (size_t)k * C_] = 0.125f * u[cc].y;
    }
  }
}

// ---------------------------------------------------------------------------
// K3/K7: complex FFT along H, cooperative. layout [(b*64+h)*33+v]*768+c
// ---------------------------------------------------------------------------
template<bool INV>
__global__ __launch_bounds__(256)
void k_fft_h(const float* __restrict__ IR, const float* __restrict__ II,
             float* __restrict__ OR_, float* __restrict__ OI_) {
  __shared__ float2 sm[64 * COLP];
  int tx = threadIdx.x & 31, r = threadIdx.x >> 5;
  int cblk = blockIdx.x % 24;
  int bv = blockIdx.x / 24;
  int vf = bv % NV, b = bv / NV;
  int c = cblk * 32 + tx;
  size_t colbase = ((size_t)b * H_ * NV + vf) * C_ + c;
  const size_t hs = (size_t)NV * C_;
  float2 v[8];
#pragma unroll
  for (int a = 0; a < 8; ++a) {
    size_t p = colbase + (size_t)(8 * a + r) * hs;
    v[a] = make_float2(IR[p], II[p]);
  }
  dft8<INV>(v);
  tw64<INV>(v, r);
#pragma unroll
  for (int d = 0; d < 8; ++d) sm[(d * 8 + r) * COLP + tx] = v[d];
  __syncthreads();
  float2 u[8];
#pragma unroll
  for (int bb = 0; bb < 8; ++bb) u[bb] = sm[(r * 8 + bb) * COLP + tx];
  dft8<INV>(u);
#pragma unroll
  for (int cc = 0; cc < 8; ++cc) {
    size_t p = colbase + (size_t)(8 * cc + r) * hs;
    OR_[p] = 0.125f * u[cc].x;
    OI_[p] = 0.125f * u[cc].y;
  }
}

// ---------------------------------------------------------------------------
// K8: irfft along W (Hermitian-extend 33 bins), accumulate into out.
// ---------------------------------------------------------------------------
__global__ __launch_bounds__(256)
void k_fft_w_inv(const float* __restrict__ YR, const float* __restrict__ YI,
                 float* __restrict__ out) {
  __shared__ float2 sm[64 * COLP];
  int tx = threadIdx.x & 31, r = threadIdx.x >> 5;
  int cblk = blockIdx.x % 24;
  int bh = blockIdx.x / 24;
  int c = cblk * 32 + tx;
  size_t ib = (size_t)bh * NV * C_ + c;
  float2 v[8];
#pragma unroll
  for (int a = 0; a < 8; ++a) {
    int n = 8 * a + r;
    if (n <= 32) {
      v[a] = make_float2(YR[ib + (size_t)n * C_], YI[ib + (size_t)n * C_]);
    } else {
      int nn = 64 - n;
      v[a] = make_float2(YR[ib + (size_t)nn * C_], -YI[ib + (size_t)nn * C_]);
    }
  }
  dft8<true>(v);
  tw64<true>(v, r);
#pragma unroll
  for (int d = 0; d < 8; ++d) sm[(d * 8 + r) * COLP + tx] = v[d];
  __syncthreads();
  float2 u[8];
#pragma unroll
  for (int bb = 0; bb < 8; ++bb) u[bb] = sm[(r * 8 + bb) * COLP + tx];
  dft8<true>(u);
  float* op = out + (size_t)bh * W_ * C_ + c;
#pragma unroll
  for (int cc = 0; cc < 8; ++cc) {
    int w = 8 * cc + r;
    op[(size_t)w * C_] += 0.125f * u[cc].x;
  }
}

// ---------------------------------------------------------------------------
// fp16 mma helpers
// ---------------------------------------------------------------------------
__device__ __forceinline__ uint32_t h2(float a, float b) {
  __half2 h = __floats2half2_rn(a, b);
  return *reinterpret_cast<uint32_t*>(&h);
}

__device__ __forceinline__ void mma_f16(float c[4],
                                        const uint32_t a[4],
                                        const uint32_t b[2]) {
  asm volatile(
      "mma.sync.aligned.m16n8k16.row.col.f32.f16.f16.f32 "
      "{%0,%1,%2,%3}, {%4,%5,%6,%7}, {%8,%9}, {%0,%1,%2,%3};"
      : "+f"(c[0]), "+f"(c[1]), "+f"(c[2]), "+f"(c[3])
      : "r"(a[0]), "r"(a[1]), "r"(a[2]), "r"(a[3]), "r"(b[0]), "r"(b[1]));
}

#define ASTR 136
#define BSTR 72

// ---------------------------------------------------------------------------
// Precompute composite layer-2 weights.
// ---------------------------------------------------------------------------
__global__ void k_precomp(const float* __restrict__ w2,
                          const float* __restrict__ b2) {
  int kb = blockIdx.x / BSZ, d = blockIdx.x % BSZ;
  int j = threadIdx.x;
  const float* W2r = w2 + (size_t)kb * BSZ * BSZ;
  const float* W2i = w2 + (size_t)NBK * BSZ * BSZ + (size_t)kb * BSZ * BSZ;
  float accC = 0.0f, accI = 0.0f;
  for (int e = 0; e < BSZ; ++e) {
    float wi = W2i[e * BSZ + j];
    accC += W2r[d * BSZ + e] * wi;
    accI += W2i[d * BSZ + e] * wi;
  }
  g_Wc [((size_t)kb * BSZ + d) * BSZ + j] = accC;
  g_Wdm[((size_t)kb * BSZ + d) * BSZ + j] = W2r[d * BSZ + j] - accI;
  if (d == 0) {
    float accB = 0.0f;
    for (int e = 0; e < BSZ; ++e) accB += b2[kb * BSZ + e] * W2i[e * BSZ + j];
    g_bp[kb * BSZ + j] = accB + b2[NBK * BSZ + kb * BSZ + j];
  }
}

// ---------------------------------------------------------------------------
// Bias GEMM (fp16 mma)
// ---------------------------------------------------------------------------
__global__ __launch_bounds__(256)
void k_gemm_bias_f16(const float* __restrict__ A, const float* __restrict__ Wt,
                     const float* __restrict__ bias, float* __restrict__ Cmat) {
  __shared__ uint32_t As2[16 * ASTR];
  __shared__ uint32_t Bs2[16 * ASTR];
  int tid = threadIdx.x;
  int lane = tid & 31, wid = tid >> 5;
  int wm = wid & 3, wn = wid >> 2;
  int gid = lane >> 2, tig = lane & 3;
  int m0 = blockIdx.x * 128, n0 = blockIdx.y * 128;

  float acc[2][8][4];
#pragma unroll
  for (int i = 0; i < 2; ++i)
#pragma unroll
    for (int j = 0; j < 8; ++j)
#pragma unroll
      for (int l = 0; l < 4; ++l) acc[i][j][l] = 0.0f;

  for (int kb = 0; kb < 768; kb += 32) {
#pragma unroll
    for (int l = 0; l < 4; ++l) {
      int f = tid + l * 256;
      int row = f >> 3, kq = f & 7;
      float4 v = *(const float4*)&A[(size_t)(m0 + row) * 768 + kb + kq * 4];
      As2[(2 * kq) * ASTR + row]     = h2(v.x, v.y);
      As2[(2 * kq + 1) * ASTR + row] = h2(v.z, v.w);
    }
#pragma unroll
    for (int l = 0; l < 4; ++l) {
      int f = tid + l * 256;
      int n = f >> 3, kq = f & 7;
      float4 v = *(const float4*)&Wt[(size_t)(n0 + n) * 768 + kb + kq * 4];
      Bs2[(2 * kq) * ASTR + n]     = h2(v.x, v.y);
      Bs2[(2 * kq + 1) * ASTR + n] = h2(v.z, v.w);
    }
    __syncthreads();
#pragma unroll
    for (int k0 = 0; k0 < 16; k0 += 8) {
      uint32_t af[2][4], bf[8][2];
#pragma unroll
      for (int mi = 0; mi < 2; ++mi) {
        int mr = wm * 32 + mi * 16 + gid;
        af[mi][0] = As2[(k0 + tig) * ASTR + mr];
        af[mi][1] = As2[(k0 + tig) * ASTR + mr + 8];
        af[mi][2] = As2[(k0 + tig + 4) * ASTR + mr];
        af[mi][3] = As2[(k0 + tig + 4) * ASTR + mr + 8];
      }
#pragma unroll
      for (int ni = 0; ni < 8; ++ni) {
        int nc = wn * 64 + ni * 8 + gid;
        bf[ni][0] = Bs2[(k0 + tig) * ASTR + nc];
        bf[ni][1] = Bs2[(k0 + tig + 4) * ASTR + nc];
      }
#pragma unroll
      for (int mi = 0; mi < 2; ++mi)
#pragma unroll
        for (int ni = 0; ni < 8; ++ni) mma_f16(acc[mi][ni], af[mi], bf[ni]);
    }
    __syncthreads();
  }
#pragma unroll
  for (int mi = 0; mi < 2; ++mi)
#pragma unroll
    for (int ni = 0; ni < 8; ++ni) {
      int row = m0 + wm * 32 + mi * 16 + gid;
      int col = n0 + wn * 64 + ni * 8 + 2 * tig;
      float b0 = bias[col], b1 = bias[col + 1];
      *(float2*)&Cmat[(size_t)row * 768 + col] =
          make_float2(acc[mi][ni][0] + b0, acc[mi][ni][1] + b1);
      *(float2*)&Cmat[(size_t)(row + 8) * 768 + col] =
          make_float2(acc[mi][ni][2] + b0, acc[mi][ni][3] + b1);
    }
}

// ---------------------------------------------------------------------------
// Fused block-diagonal complex-MLP pass (fp16 mma), two outputs.
// ---------------------------------------------------------------------------
__global__ __launch_bounds__(256)
void k_mlp2(const float* __restrict__ P, const float* __restrict__ Q,
            const float* __restrict__ WRa, const float* __restrict__ WRb, float sR,
            const float* __restrict__ WIa, const float* __restrict__ WIb, float sI,
            const float* __restrict__ bR, const float* __restrict__ bI, int relu,
            float* __restrict__ OutR, float* __restrict__ OutI) {
  __shared__ uint32_t As2[16 * ASTR];
  __shared__ uint32_t BsR[16 * BSTR];
  __shared__ uint32_t BsI[16 * BSTR];
  int tid = threadIdx.x;
  int lane = tid & 31, wid = tid >> 5;
  int wm = wid & 3, wn = wid >> 2;
  int gid = lane >> 2, tig = lane & 3;
  int m0 = blockIdx.x * 128;
  int nt = blockIdx.y;
  int kb = nt / 3, j0 = (nt % 3) * 64;

  float accR[2][4][4], accI[2][4][4];
#pragma unroll
  for (int i = 0; i < 2; ++i)
#pragma unroll
    for (int j = 0; j < 4; ++j)
#pragma unroll
      for (int l = 0; l < 4; ++l) { accR[i][j][l] = 0.0f; accI[i][j][l] = 0.0f; }

#pragma unroll
  for (int ph = 0; ph < 2; ++ph) {
    const float* Ap = ph ? Q : P;
    const float* Wr = ph ? WRb : WRa;
    const float* Wi = ph ? WIb : WIa;
    float sr = ph ? sR : 1.0f;
    float si = ph ? sI : 1.0f;
    for (int kk = 0; kk < 192; kk += 32) {
#pragma unroll
      for (int l = 0; l < 4; ++l) {
        int f = tid + l * 256;
        int row = f >> 3, kq = f & 7;
        float4 v = *(const float4*)&Ap[(size_t)(m0 + row) * 768 +
                                       kb * 192 + kk + kq * 4];
        As2[(2 * kq) * ASTR + row]     = h2(v.x, v.y);
        As2[(2 * kq + 1) * ASTR + row] = h2(v.z, v.w);
      }
      {
        int kp = tid >> 4, nq = tid & 15;
        size_t base = (size_t)(kb * 192 + kk + 2 * kp) * 192 + j0 + nq * 4;
        float4 r0 = *(const float4*)&Wr[base];
        float4 r1 = *(const float4*)&Wr[base + 192];
        BsR[kp * BSTR + nq * 4 + 0] = h2(sr * r0.x, sr * r1.x);
        BsR[kp * BSTR + nq * 4 + 1] = h2(sr * r0.y, sr * r1.y);
        BsR[kp * BSTR + nq * 4 + 2] = h2(sr * r0.z, sr * r1.z);
        BsR[kp * BSTR + nq * 4 + 3] = h2(sr * r0.w, sr * r1.w);
        float4 s0 = *(const float4*)&Wi[base];
        float4 s1 = *(const float4*)&Wi[base + 192];
        BsI[kp * BSTR + nq * 4 + 0] = h2(si * s0.x, si * s1.x);
        BsI[kp * BSTR + nq * 4 + 1] = h2(si * s0.y, si * s1.y);
        BsI[kp * BSTR + nq * 4 + 2] = h2(si * s0.z, si * s1.z);
        BsI[kp * BSTR + nq * 4 + 3] = h2(si * s0.w, si * s1.w);
      }
      __syncthreads();
#pragma unroll
      for (int k0 = 0; k0 < 16; k0 += 8) {
        uint32_t af[2][4], bfR[4][2], bfI[4][2];
#pragma unroll
        for (int mi = 0; mi < 2; ++mi) {
          int mr = wm * 32 + mi * 16 + gid;
          af[mi][0] = As2[(k0 + tig) * ASTR + mr];
          af[mi][1] = As2[(k0 + tig) * ASTR + mr + 8];
          af[mi][2] = As2[(k0 + tig + 4) * ASTR + mr];
          af[mi][3] = As2[(k0 + tig + 4) * ASTR + mr + 8];
        }
#pragma unroll
        for (int ni = 0; ni < 4; ++ni) {
          int nc = wn * 32 + ni * 8 + gid;
          bfR[ni][0] = BsR[(k0 + tig) * BSTR + nc];
          bfR[ni][1] = BsR[(k0 + tig + 4) * BSTR + nc];
          bfI[ni][0] = BsI[(k0 + tig) * BSTR + nc];
          bfI[ni][1] = BsI[(k0 + tig + 4) * BSTR + nc];
        }
#pragma unroll
        for (int mi = 0; mi < 2; ++mi)
#pragma unroll
          for (int ni = 0; ni < 4; ++ni) {
            mma_f16(accR[mi][ni], af[mi], bfR[ni]);
            mma_f16(accI[mi][ni], af[mi], bfI[ni]);
          }
      }
      __syncthreads();
    }
  }
#pragma unroll
  for (int mi = 0; mi < 2; ++mi)
#pragma unroll
    for (int ni = 0; ni < 4; ++ni) {
      int row = m0 + wm * 32 + mi * 16 + gid;
      int colb = j0 + wn * 32 + ni * 8 + 2 * tig;
      size_t cg = (size_t)kb * 192 + colb;
      float bR0 = bR[kb * 192 + colb], bR1 = bR[kb * 192 + colb + 1];
      float bI0 = bI[kb * 192 + colb], bI1 = bI[kb * 192 + colb + 1];
      float r0 = accR[mi][ni][0] + bR0, r1 = accR[mi][ni][1] + bR1;
      float r2v = accR[mi][ni][2] + bR0, r3 = accR[mi][ni][3] + bR1;
      float i0 = accI[mi][ni][0] + bI0, i1v = accI[mi][ni][1] + bI1;
      float i2v = accI[mi][ni][2] + bI0, i3 = accI[mi][ni][3] + bI1;
      if (relu) {
        r0 = fmaxf(r0, 0.0f); r1 = fmaxf(r1, 0.0f);
        r2v = fmaxf(r2v, 0.0f); r3 = fmaxf(r3, 0.0f);
        i0 = fmaxf(i0, 0.0f); i1v = fmaxf(i1v, 0.0f);
        i2v = fmaxf(i2v, 0.0f); i3 = fmaxf(i3, 0.0f);
      }
      *(float2*)&OutR[(size_t)row * 768 + cg]       = make_float2(r0, r1);
      *(float2*)&OutR[(size_t)(row + 8) * 768 + cg] = make_float2(r2v, r3);
      *(float2*)&OutI[(size_t)row * 768 + cg]       = make_float2(i0, i1v);
      *(float2*)&OutI[(size_t)(row + 8) * 768 + cg] = make_float2(i2v, i3);
    }
}

// ---------------------------------------------------------------------------
extern "C" void kernel_launch(void* const* d_in, const int* in_sizes, int n_in,
                              void* d_out, int out_size) {
  const float* x  = (const float*)d_in[0];
  const float* w1 = (const float*)d_in[1];
  const float* b1 = (const float*)d_in[2];
  const float* w2 = (const float*)d_in[3];
  const float* b2 = (const float*)d_in[4];
  const float* bw = (const float*)d_in[5];
  const float* bb = (const float*)d_in[6];
  float* out = (float*)d_out;

  float *SAR, *SAI, *SBR, *SBI, *Wc, *Wdm, *bp;
  cudaGetSymbolAddress((void**)&SAR, g_SAR);
  cudaGetSymbolAddress((void**)&SAI, g_SAI);
  cudaGetSymbolAddress((void**)&SBR, g_SBR);
  cudaGetSymbolAddress((void**)&SBI, g_SBI);
  cudaGetSymbolAddress((void**)&Wc,  g_Wc);
  cudaGetSymbolAddress((void**)&Wdm, g_Wdm);
  cudaGetSymbolAddress((void**)&bp,  g_bp);

  const int WOFF = NBK * BSZ * BSZ;
  const int BOFF = NBK * BSZ;

  // 1) bias GEMM -> out
  k_gemm_bias_f16<<<dim3(NROW / 128, 6), 256>>>(x, bw, bb, out);

  // 2) forward rfft along W  (x -> SB)   8 thr/col cooperative
  k_fft_w_fwd<<<(B_ * H_) * (C_ / 32), 256>>>(x, SBR, SBI);

  // 3) composite layer-2 weights
  k_precomp<<<NBK * BSZ, BSZ>>>(w2, b2);

  // 4) forward fft along H   (SB -> SA)
  k_fft_h<false><<<(B_ * NV) * (C_ / 32), 256>>>(SBR, SBI, SAR, SAI);

  // 5) layer 1 fused
  k_mlp2<<<dim3(MTOK / 128, 12), 256>>>(SAR, SAI,
                                        w1, w1 + WOFF, -1.0f,
                                        w1 + WOFF, w1, 1.0f,
                                        b1, b1 + BOFF, 1, SBR, SBI);

  // 6) layer 2 fused (i2 via composite weights == r2·W2i + i1·W2r + b2i)
  k_mlp2<<<dim3(MTOK / 128, 12), 256>>>(SBR, SBI,
                                        w2, w2 + WOFF, -1.0f,
                                        Wc, Wdm, 1.0f,
                                        b2, bp, 0, SAR, SAI);

  // 7) inverse fft along H   (SA -> SB)
  k_fft_h<true><<<(B_ * NV) * (C_ / 32), 256>>>(SAR, SAI, SBR, SBI);

  // 8) inverse rfft along W, accumulate into out
  k_fft_w_inv<<<(B_ * H_) * (C_ / 32), 256>>>(SBR, SBI, out);
}

// round 6
// speedup vs baseline: 5.1830x; 1.1307x over previous
#include <cuda_runtime.h>
#include <cuda_fp16.h>
#include <cstdint>
#include <cstddef>

// ---------------------------------------------------------------------------
// AFNO: out = irfft2( MLP( rfft2(x) ) ) + (x @ bias_w^T + bias_b)
// B=8, H=W=64, C=768, 4 blocks of 192.
// Spectral scratch: interleaved __half2(R,I). GEMMs: fp16 mma m16n8k16.
// ---------------------------------------------------------------------------

#define B_ 8
#define H_ 64
#define W_ 64
#define C_ 768
#define NBK 4
#define BSZ 192
#define NV 33
#define MTOK (B_ * H_ * NV)     /* 16896 */
#define NROW (B_ * H_ * W_)     /* 32768 */

__device__ __half2 g_SA[MTOK * C_];   // X / (r2,i2)
__device__ __half2 g_SB[MTOK * C_];   // Fw / (r1,i1) / Y
__device__ float g_Wc [NBK * BSZ * BSZ];
__device__ float g_Wdm[NBK * BSZ * BSZ];
__device__ float g_bp [NBK * BSZ];

// W64^k = e^{-2pi i k/64}: TW64R = cos, TW64I = -sin, k = 0..63
__constant__ float TW64R[64] = {
  1.0f, 0.99518472667f, 0.98078528040f, 0.95694033573f,
  0.92387953251f, 0.88192126435f, 0.83146961230f, 0.77301045336f,
  0.70710678119f, 0.63439328416f, 0.55557023302f, 0.47139673683f,
  0.38268343236f, 0.29028467725f, 0.19509032202f, 0.09801714033f,
  0.0f, -0.09801714033f, -0.19509032202f, -0.29028467725f,
  -0.38268343236f, -0.47139673683f, -0.55557023302f, -0.63439328416f,
  -0.70710678119f, -0.77301045336f, -0.83146961230f, -0.88192126435f,
  -0.92387953251f, -0.95694033573f, -0.98078528040f, -0.99518472667f,
  -1.0f, -0.99518472667f, -0.98078528040f, -0.95694033573f,
  -0.92387953251f, -0.88192126435f, -0.83146961230f, -0.77301045336f,
  -0.70710678119f, -0.63439328416f, -0.55557023302f, -0.47139673683f,
  -0.38268343236f, -0.29028467725f, -0.19509032202f, -0.09801714033f,
  0.0f, 0.09801714033f, 0.19509032202f, 0.29028467725f,
  0.38268343236f, 0.47139673683f, 0.55557023302f, 0.63439328416f,
  0.70710678119f, 0.77301045336f, 0.83146961230f, 0.88192126435f,
  0.92387953251f, 0.95694033573f, 0.98078528040f, 0.99518472667f
};
__constant__ float TW64I[64] = {
  -0.0f, -0.09801714033f, -0.19509032202f, -0.29028467725f,
  -0.38268343236f, -0.47139673683f, -0.55557023302f, -0.63439328416f,
  -0.70710678119f, -0.77301045336f, -0.83146961230f, -0.88192126435f,
  -0.92387953251f, -0.95694033573f, -0.98078528040f, -0.99518472667f,
  -1.0f, -0.99518472667f, -0.98078528040f, -0.95694033573f,
  -0.92387953251f, -0.88192126435f, -0.83146961230f, -0.77301045336f,
  -0.70710678119f, -0.63439328416f, -0.55557023302f, -0.47139673683f,
  -0.38268343236f, -0.29028467725f, -0.19509032202f, -0.09801714033f,
  0.0f, 0.09801714033f, 0.19509032202f, 0.29028467725f,
  0.38268343236f, 0.47139673683f, 0.55557023302f, 0.63439328416f,
  0.70710678119f, 0.77301045336f, 0.83146961230f, 0.88192126435f,
  0.92387953251f, 0.95694033573f, 0.98078528040f, 0.99518472667f,
  1.0f, 0.99518472667f, 0.98078528040f, 0.95694033573f,
  0.92387953251f, 0.88192126435f, 0.83146961230f, 0.77301045336f,
  0.70710678119f, 0.63439328416f, 0.55557023302f, 0.47139673683f,
  0.38268343236f, 0.29028467725f, 0.19509032202f, 0.09801714033f
};
__constant__ float TW8R[4] = {1.0f, 0.70710678119f, 0.0f, -0.70710678119f};
__constant__ float TW8I[4] = {0.0f, -0.70710678119f, -1.0f, -0.70710678119f};

template<bool INV>
__device__ __forceinline__ void dft8(float2 v[8]) {
  float2 t;
  t = v[1]; v[1] = v[4]; v[4] = t;
  t = v[3]; v[3] = v[6]; v[6] = t;
#pragma unroll
  for (int s = 1; s <= 3; ++s) {
    const int m = 1 << s, half = m >> 1, stp = 8 >> s;
#pragma unroll
    for (int g = 0; g < 8; g += m)
#pragma unroll
      for (int q = 0; q < half; ++q) {
        float wr = TW8R[q * stp];
        float wi = INV ? -TW8I[q * stp] : TW8I[q * stp];
        float2 bb = v[g + q + half];
        float tr = bb.x * wr - bb.y * wi;
        float ti = bb.x * wi + bb.y * wr;
        float2 aa = v[g + q];
        v[g + q]        = make_float2(aa.x + tr, aa.y + ti);
        v[g + q + half] = make_float2(aa.x - tr, aa.y - ti);
      }
  }
}

template<bool INV>
__device__ __forceinline__ void tw64(float2 v[8], int r) {
#pragma unroll
  for (int d = 1; d < 8; ++d) {
    int k = r * d;
    float wr = TW64R[k];
    float wi = INV ? -TW64I[k] : TW64I[k];
    float2 z = v[d];
    v[d] = make_float2(z.x * wr - z.y * wi, z.x * wi + z.y * wr);
  }
}

__device__ __forceinline__ __half2 pack05(float2 u) {
  return __floats2half2_rn(0.125f * u.x, 0.125f * u.y);
}

#define COLP 33

// ---------------------------------------------------------------------------
// K2: rfft along W: x (fp32) -> SB (half2), v=0..32, scale 1/8
// ---------------------------------------------------------------------------
__global__ __launch_bounds__(256)
void k_fft_w_fwd(const float* __restrict__ x, __half2* __restrict__ F) {
  __shared__ float2 sm[64 * COLP];
  int tx = threadIdx.x & 31, r = threadIdx.x >> 5;
  int cblk = blockIdx.x % 24;
  int bh = blockIdx.x / 24;
  int c = cblk * 32 + tx;
  const float* xp = x + (size_t)bh * W_ * C_ + c;
  float2 v[8];
#pragma unroll
  for (int a = 0; a < 8; ++a)
    v[a] = make_float2(xp[(size_t)(8 * a + r) * C_], 0.0f);
  dft8<false>(v);
  tw64<false>(v, r);
#pragma unroll
  for (int d = 0; d < 8; ++d) sm[(d * 8 + r) * COLP + tx] = v[d];
  __syncthreads();
  float2 u[8];
#pragma unroll
  for (int b = 0; b < 8; ++b) u[b] = sm[(r * 8 + b) * COLP + tx];
  dft8<false>(u);
  size_t ob = (size_t)bh * NV * C_ + c;
#pragma unroll
  for (int cc = 0; cc < 8; ++cc) {
    int k = 8 * cc + r;
    if (k <= 32) F[ob + (size_t)k * C_] = pack05(u[cc]);
  }
}

// ---------------------------------------------------------------------------
// K3/K7: complex FFT along H, half2 I/O
// ---------------------------------------------------------------------------
template<bool INV>
__global__ __launch_bounds__(256)
void k_fft_h(const __half2* __restrict__ I, __half2* __restrict__ O) {
  __shared__ float2 sm[64 * COLP];
  int tx = threadIdx.x & 31, r = threadIdx.x >> 5;
  int cblk = blockIdx.x % 24;
  int bv = blockIdx.x / 24;
  int vf = bv % NV, b = bv / NV;
  int c = cblk * 32 + tx;
  size_t colbase = ((size_t)b * H_ * NV + vf) * C_ + c;
  const size_t hs = (size_t)NV * C_;
  float2 v[8];
#pragma unroll
  for (int a = 0; a < 8; ++a)
    v[a] = __half22float2(I[colbase + (size_t)(8 * a + r) * hs]);
  dft8<INV>(v);
  tw64<INV>(v, r);
#pragma unroll
  for (int d = 0; d < 8; ++d) sm[(d * 8 + r) * COLP + tx] = v[d];
  __syncthreads();
  float2 u[8];
#pragma unroll
  for (int bb = 0; bb < 8; ++bb) u[bb] = sm[(r * 8 + bb) * COLP + tx];
  dft8<INV>(u);
#pragma unroll
  for (int cc = 0; cc < 8; ++cc)
    O[colbase + (size_t)(8 * cc + r) * hs] = pack05(u[cc]);
}

// ---------------------------------------------------------------------------
// K8: irfft along W (half2 in), accumulate into fp32 out
// ---------------------------------------------------------------------------
__global__ __launch_bounds__(256)
void k_fft_w_inv(const __half2* __restrict__ Y, float* __restrict__ out) {
  __shared__ float2 sm[64 * COLP];
  int tx = threadIdx.x & 31, r = threadIdx.x >> 5;
  int cblk = blockIdx.x % 24;
  int bh = blockIdx.x / 24;
  int c = cblk * 32 + tx;
  size_t ib = (size_t)bh * NV * C_ + c;
  float2 v[8];
#pragma unroll
  for (int a = 0; a < 8; ++a) {
    int n = 8 * a + r;
    if (n <= 32) {
      v[a] = __half22float2(Y[ib + (size_t)n * C_]);
    } else {
      float2 z = __half22float2(Y[ib + (size_t)(64 - n) * C_]);
      v[a] = make_float2(z.x, -z.y);
    }
  }
  dft8<true>(v);
  tw64<true>(v, r);
#pragma unroll
  for (int d = 0; d < 8; ++d) sm[(d * 8 + r) * COLP + tx] = v[d];
  __syncthreads();
  float2 u[8];
#pragma unroll
  for (int bb = 0; bb < 8; ++bb) u[bb] = sm[(r * 8 + bb) * COLP + tx];
  dft8<true>(u);
  float* op = out + (size_t)bh * W_ * C_ + c;
#pragma unroll
  for (int cc = 0; cc < 8; ++cc)
    op[(size_t)(8 * cc + r) * C_] += 0.125f * u[cc].x;
}

// ---------------------------------------------------------------------------
// fp16 mma helpers
// ---------------------------------------------------------------------------
__device__ __forceinline__ uint32_t h2(float a, float b) {
  __half2 h = __floats2half2_rn(a, b);
  return *reinterpret_cast<uint32_t*>(&h);
}

__device__ __forceinline__ void mma_f16(float c[4],
                                        const uint32_t a[4],
                                        const uint32_t b[2]) {
  asm volatile(
      "mma.sync.aligned.m16n8k16.row.col.f32.f16.f16.f32 "
      "{%0,%1,%2,%3}, {%4,%5,%6,%7}, {%8,%9}, {%0,%1,%2,%3};"
      : "+f"(c[0]), "+f"(c[1]), "+f"(c[2]), "+f"(c[3])
      : "r"(a[0]), "r"(a[1]), "r"(a[2]), "r"(a[3]), "r"(b[0]), "r"(b[1]));
}

#define ASTR 136
#define BSTR 72

// ---------------------------------------------------------------------------
// Precompute composite layer-2 weights.
// ---------------------------------------------------------------------------
__global__ void k_precomp(const float* __restrict__ w2,
                          const float* __restrict__ b2) {
  int kb = blockIdx.x / BSZ, d = blockIdx.x % BSZ;
  int j = threadIdx.x;
  const float* W2r = w2 + (size_t)kb * BSZ * BSZ;
  const float* W2i = w2 + (size_t)NBK * BSZ * BSZ + (size_t)kb * BSZ * BSZ;
  float accC = 0.0f, accI = 0.0f;
  for (int e = 0; e < BSZ; ++e) {
    float wi = W2i[e * BSZ + j];
    accC += W2r[d * BSZ + e] * wi;
    accI += W2i[d * BSZ + e] * wi;
  }
  g_Wc [((size_t)kb * BSZ + d) * BSZ + j] = accC;
  g_Wdm[((size_t)kb * BSZ + d) * BSZ + j] = W2r[d * BSZ + j] - accI;
  if (d == 0) {
    float accB = 0.0f;
    for (int e = 0; e < BSZ; ++e) accB += b2[kb * BSZ + e] * W2i[e * BSZ + j];
    g_bp[kb * BSZ + j] = accB + b2[NBK * BSZ + kb * BSZ + j];
  }
}

// ---------------------------------------------------------------------------
// Bias GEMM (fp16 mma), unchanged
// ---------------------------------------------------------------------------
__global__ __launch_bounds__(256)
void k_gemm_bias_f16(const float* __restrict__ A, const float* __restrict__ Wt,
                     const float* __restrict__ bias, float* __restrict__ Cmat) {
  __shared__ uint32_t As2[16 * ASTR];
  __shared__ uint32_t Bs2[16 * ASTR];
  int tid = threadIdx.x;
  int lane = tid & 31, wid = tid >> 5;
  int wm = wid & 3, wn = wid >> 2;
  int gid = lane >> 2, tig = lane & 3;
  int m0 = blockIdx.x * 128, n0 = blockIdx.y * 128;

  float acc[2][8][4];
#pragma unroll
  for (int i = 0; i < 2; ++i)
#pragma unroll
    for (int j = 0; j < 8; ++j)
#pragma unroll
      for (int l = 0; l < 4; ++l) acc[i][j][l] = 0.0f;

  for (int kb = 0; kb < 768; kb += 32) {
#pragma unroll
    for (int l = 0; l < 4; ++l) {
      int f = tid + l * 256;
      int row = f >> 3, kq = f & 7;
      float4 v = *(const float4*)&A[(size_t)(m0 + row) * 768 + kb + kq * 4];
      As2[(2 * kq) * ASTR + row]     = h2(v.x, v.y);
      As2[(2 * kq + 1) * ASTR + row] = h2(v.z, v.w);
    }
#pragma unroll
    for (int l = 0; l < 4; ++l) {
      int f = tid + l * 256;
      int n = f >> 3, kq = f & 7;
      float4 v = *(const float4*)&Wt[(size_t)(n0 + n) * 768 + kb + kq * 4];
      Bs2[(2 * kq) * ASTR + n]     = h2(v.x, v.y);
      Bs2[(2 * kq + 1) * ASTR + n] = h2(v.z, v.w);
    }
    __syncthreads();
#pragma unroll
    for (int k0 = 0; k0 < 16; k0 += 8) {
      uint32_t af[2][4], bf[8][2];
#pragma unroll
      for (int mi = 0; mi < 2; ++mi) {
        int mr = wm * 32 + mi * 16 + gid;
        af[mi][0] = As2[(k0 + tig) * ASTR + mr];
        af[mi][1] = As2[(k0 + tig) * ASTR + mr + 8];
        af[mi][2] = As2[(k0 + tig + 4) * ASTR + mr];
        af[mi][3] = As2[(k0 + tig + 4) * ASTR + mr + 8];
      }
#pragma unroll
      for (int ni = 0; ni < 8; ++ni) {
        int nc = wn * 64 + ni * 8 + gid;
        bf[ni][0] = Bs2[(k0 + tig) * ASTR + nc];
        bf[ni][1] = Bs2[(k0 + tig + 4) * ASTR + nc];
      }
#pragma unroll
      for (int mi = 0; mi < 2; ++mi)
#pragma unroll
        for (int ni = 0; ni < 8; ++ni) mma_f16(acc[mi][ni], af[mi], bf[ni]);
    }
    __syncthreads();
  }
#pragma unroll
  for (int mi = 0; mi < 2; ++mi)
#pragma unroll
    for (int ni = 0; ni < 8; ++ni) {
      int row = m0 + wm * 32 + mi * 16 + gid;
      int col = n0 + wn * 64 + ni * 8 + 2 * tig;
      float b0 = bias[col], b1 = bias[col + 1];
      *(float2*)&Cmat[(size_t)row * 768 + col] =
          make_float2(acc[mi][ni][0] + b0, acc[mi][ni][1] + b1);
      *(float2*)&Cmat[(size_t)(row + 8) * 768 + col] =
          make_float2(acc[mi][ni][2] + b0, acc[mi][ni][3] + b1);
    }
}

// ---------------------------------------------------------------------------
// Fused complex-MLP pass, half2-interleaved A and Out:
//   r = act( P·WRa + sR*Q·WRb + bR ),  i = act( P·WIa + sI*Q·WIb + bI )
// where A[t,c] = half2(P, Q). Out[t,c] = half2(r, i).
// Single pass over K: A loaded once for both P and Q phases.
// ---------------------------------------------------------------------------
__global__ __launch_bounds__(256)
void k_mlp2(const __half2* __restrict__ A,
            const float* __restrict__ WRa, const float* __restrict__ WRb, float sR,
            const float* __restrict__ WIa, const float* __restrict__ WIb, float sI,
            const float* __restrict__ bR, const float* __restrict__ bI, int relu,
            __half2* __restrict__ Out) {
  __shared__ uint32_t AsP[16 * ASTR];
  __shared__ uint32_t AsQ[16 * ASTR];
  __shared__ uint32_t BRa[16 * BSTR];
  __shared__ uint32_t BRb[16 * BSTR];
  __shared__ uint32_t BIa[16 * BSTR];
  __shared__ uint32_t BIb[16 * BSTR];
  int tid = threadIdx.x;
  int lane = tid & 31, wid = tid >> 5;
  int wm = wid & 3, wn = wid >> 2;
  int gid = lane >> 2, tig = lane & 3;
  int m0 = blockIdx.x * 128;
  int nt = blockIdx.y;
  int kb = nt / 3, j0 = (nt % 3) * 64;

  float accR[2][4][4], accI[2][4][4];
#pragma unroll
  for (int i = 0; i < 2; ++i)
#pragma unroll
    for (int j = 0; j < 4; ++j)
#pragma unroll
      for (int l = 0; l < 4; ++l) { accR[i][j][l] = 0.0f; accI[i][j][l] = 0.0f; }

  for (int kk = 0; kk < 192; kk += 32) {
    // A tile: 128 rows x 32 cols half2(P,Q). One uint4 = 4 cols. 4 per thread.
#pragma unroll
    for (int l = 0; l < 4; ++l) {
      int f = tid + l * 256;
      int row = f >> 3, kq = f & 7;
      uint4 raw = *(const uint4*)&A[(size_t)(m0 + row) * 768 +
                                    kb * 192 + kk + kq * 4];
      __half2 q0 = *reinterpret_cast<__half2*>(&raw.x);
      __half2 q1 = *reinterpret_cast<__half2*>(&raw.y);
      __half2 q2 = *reinterpret_cast<__half2*>(&raw.z);
      __half2 q3 = *reinterpret_cast<__half2*>(&raw.w);
      __half2 p01 = __lows2half2(q0, q1),  qq01 = __highs2half2(q0, q1);
      __half2 p23 = __lows2half2(q2, q3),  qq23 = __highs2half2(q2, q3);
      AsP[(2 * kq) * ASTR + row]     = *reinterpret_cast<uint32_t*>(&p01);
      AsP[(2 * kq + 1) * ASTR + row] = *reinterpret_cast<uint32_t*>(&p23);
      AsQ[(2 * kq) * ASTR + row]     = *reinterpret_cast<uint32_t*>(&qq01);
      AsQ[(2 * kq + 1) * ASTR + row] = *reinterpret_cast<uint32_t*>(&qq23);
    }
    // B tiles: 4 weight tiles of 32k x 64n. kp = tid>>4 (0..15), nq = tid&15.
    {
      int kp = tid >> 4, nq = tid & 15;
      size_t base = (size_t)(kb * 192 + kk + 2 * kp) * 192 + j0 + nq * 4;
#pragma unroll
      for (int t = 0; t < 4; ++t) {
        const float* W = (t == 0) ? WRa : (t == 1) ? WRb : (t == 2) ? WIa : WIb;
        float s = (t == 1) ? sR : (t == 3) ? sI : 1.0f;
        uint32_t* Bs = (t == 0) ? BRa : (t == 1) ? BRb : (t == 2) ? BIa : BIb;
        float4 r0 = *(const float4*)&W[base];
        float4 r1 = *(const float4*)&W[base + 192];
        Bs[kp * BSTR + nq * 4 + 0] = h2(s * r0.x, s * r1.x);
        Bs[kp * BSTR + nq * 4 + 1] = h2(s * r0.y, s * r1.y);
        Bs[kp * BSTR + nq * 4 + 2] = h2(s * r0.z, s * r1.z);
        Bs[kp * BSTR + nq * 4 + 3] = h2(s * r0.w, s * r1.w);
      }
    }
    __syncthreads();
#pragma unroll
    for (int k0 = 0; k0 < 16; k0 += 8) {
      uint32_t afP[2][4], afQ[2][4], bRa[4][2], bRb[4][2], bIa[4][2], bIb[4][2];
#pragma unroll
      for (int mi = 0; mi < 2; ++mi) {
        int mr = wm * 32 + mi * 16 + gid;
        afP[mi][0] = AsP[(k0 + tig) * ASTR + mr];
        afP[mi][1] = AsP[(k0 + tig) * ASTR + mr + 8];
        afP[mi][2] = AsP[(k0 + tig + 4) * ASTR + mr];
        afP[mi][3] = AsP[(k0 + tig + 4) * ASTR + mr + 8];
        afQ[mi][0] = AsQ[(k0 + tig) * ASTR + mr];
        afQ[mi][1] = AsQ[(k0 + tig) * ASTR + mr + 8];
        afQ[mi][2] = AsQ[(k0 + tig + 4) * ASTR + mr];
        afQ[mi][3] = AsQ[(k0 + tig + 4) * ASTR + mr + 8];
      }
#pragma unroll
      for (int ni = 0; ni < 4; ++ni) {
        int nc = wn * 32 + ni * 8 + gid;
        bRa[ni][0] = BRa[(k0 + tig) * BSTR + nc];
        bRa[ni][1] = BRa[(k0 + tig + 4) * BSTR + nc];
        bRb[ni][0] = BRb[(k0 + tig) * BSTR + nc];
        bRb[ni][1] = BRb[(k0 + tig + 4) * BSTR + nc];
        bIa[ni][0] = BIa[(k0 + tig) * BSTR + nc];
        bIa[ni][1] = BIa[(k0 + tig + 4) * BSTR + nc];
        bIb[ni][0] = BIb[(k0 + tig) * BSTR + nc];
        bIb[ni][1] = BIb[(k0 + tig + 4) * BSTR + nc];
      }
#pragma unroll
      for (int mi = 0; mi < 2; ++mi)
#pragma unroll
        for (int ni = 0; ni < 4; ++ni) {
          mma_f16(accR[mi][ni], afP[mi], bRa[ni]);
          mma_f16(accR[mi][ni], afQ[mi], bRb[ni]);
          mma_f16(accI[mi][ni], afP[mi], bIa[ni]);
          mma_f16(accI[mi][ni], afQ[mi], bIb[ni]);
        }
    }
    __syncthreads();
  }
#pragma unroll
  for (int mi = 0; mi < 2; ++mi)
#pragma unroll
    for (int ni = 0; ni < 4; ++ni) {
      int row = m0 + wm * 32 + mi * 16 + gid;
      int colb = j0 + wn * 32 + ni * 8 + 2 * tig;
      size_t cg = (size_t)kb * 192 + colb;
      float bR0 = bR[kb * 192 + colb], bR1 = bR[kb * 192 + colb + 1];
      float bI0 = bI[kb * 192 + colb], bI1 = bI[kb * 192 + colb + 1];
      float r0 = accR[mi][ni][0] + bR0, r1 = accR[mi][ni][1] + bR1;
      float r2v = accR[mi][ni][2] + bR0, r3 = accR[mi][ni][3] + bR1;
      float i0 = accI[mi][ni][0] + bI0, i1v = accI[mi][ni][1] + bI1;
      float i2v = accI[mi][ni][2] + bI0, i3 = accI[mi][ni][3] + bI1;
      if (relu) {
        r0 = fmaxf(r0, 0.0f); r1 = fmaxf(r1, 0.0f);
        r2v = fmaxf(r2v, 0.0f); r3 = fmaxf(r3, 0.0f);
        i0 = fmaxf(i0, 0.0f); i1v = fmaxf(i1v, 0.0f);
        i2v = fmaxf(i2v, 0.0f); i3 = fmaxf(i3, 0.0f);
      }
      uint2 o0 = make_uint2(h2(r0, i0), h2(r1, i1v));
      uint2 o1 = make_uint2(h2(r2v, i2v), h2(r3, i3));
      *(uint2*)&Out[(size_t)row * 768 + cg]       = o0;
      *(uint2*)&Out[(size_t)(row + 8) * 768 + cg] = o1;
    }
}

// ---------------------------------------------------------------------------
extern "C" void kernel_launch(void* const* d_in, const int* in_sizes, int n_in,
                              void* d_out, int out_size) {
  const float* x  = (const float*)d_in[0];
  const float* w1 = (const float*)d_in[1];
  const float* b1 = (const float*)d_in[2];
  const float* w2 = (const float*)d_in[3];
  const float* b2 = (const float*)d_in[4];
  const float* bw = (const float*)d_in[5];
  const float* bb = (const float*)d_in[6];
  float* out = (float*)d_out;

  __half2 *SA, *SB;
  float *Wc, *Wdm, *bp;
  cudaGetSymbolAddress((void**)&SA, g_SA);
  cudaGetSymbolAddress((void**)&SB, g_SB);
  cudaGetSymbolAddress((void**)&Wc,  g_Wc);
  cudaGetSymbolAddress((void**)&Wdm, g_Wdm);
  cudaGetSymbolAddress((void**)&bp,  g_bp);

  const int WOFF = NBK * BSZ * BSZ;
  const int BOFF = NBK * BSZ;

  // 1) bias GEMM -> out
  k_gemm_bias_f16<<<dim3(NROW / 128, 6), 256>>>(x, bw, bb, out);

  // 2) forward rfft along W (x -> SB)
  k_fft_w_fwd<<<(B_ * H_) * (C_ / 32), 256>>>(x, SB);

  // 3) composite layer-2 weights
  k_precomp<<<NBK * BSZ, BSZ>>>(w2, b2);

  // 4) forward fft along H (SB -> SA)
  k_fft_h<false><<<(B_ * NV) * (C_ / 32), 256>>>(SB, SA);

  // 5) layer 1: (Xr,Xi) -> (r1,i1)
  k_mlp2<<<dim3(MTOK / 128, 12), 256>>>(SA,
                                        w1, w1 + WOFF, -1.0f,
                                        w1 + WOFF, w1, 1.0f,
                                        b1, b1 + BOFF, 1, SB);

  // 6) layer 2: (r1,i1) -> (r2,i2)  (i2 via composite weights)
  k_mlp2<<<dim3(MTOK / 128, 12), 256>>>(SB,
                                        w2, w2 + WOFF, -1.0f,
                                        Wc, Wdm, 1.0f,
                                        b2, bp, 0, SA);

  // 7) inverse fft along H (SA -> SB)
  k_fft_h<true><<<(B_ * NV) * (C_ / 32), 256>>>(SA, SB);

  // 8) inverse rfft along W, accumulate into out
  k_fft_w_inv<<<(B_ * H_) * (C_ / 32), 256>>>(SB, out);
}